// round 13
// baseline (speedup 1.0000x reference)
#include <cuda_runtime.h>
#include <cuda_bf16.h>
#include <cuda_fp16.h>
#include <mma.h>
#include <math.h>
#include <stdint.h>

using namespace nvcuda;

#define NSEQ 1024
#define DMOD 512
#define NHEAD 16
#define HDIM 32
#define DZ 128
#define NN (NSEQ*NSEQ)
#define QSCALE 0.17677669529663687f

typedef unsigned long long u64;
typedef __nv_bfloat16 bf16;

__device__ float g_gate[NSEQ*DMOD];
__device__ __half g_scoresh[NHEAD*NN];
__device__ float g_wzp[DZ*NHEAD];
__device__ float g_alpha[NHEAD];
__device__ float g_beta[NHEAD];
__device__ bf16 g_sa_hi[NSEQ*DMOD], g_sa_lo[NSEQ*DMOD];
__device__ bf16 g_oa_hi[NSEQ*DMOD], g_oa_lo[NSEQ*DMOD];
__device__ bf16 g_wt_hi[5*DMOD*DMOD], g_wt_lo[5*DMOD*DMOD];
__device__ bf16 g_qh[NHEAD*NSEQ*HDIM], g_ql[NHEAD*NSEQ*HDIM];
__device__ bf16 g_kh[NHEAD*NSEQ*HDIM], g_kl[NHEAD*NSEQ*HDIM];
__device__ bf16 g_vh[NHEAD*NSEQ*HDIM], g_vl[NHEAD*NSEQ*HDIM];

__device__ __forceinline__ uint32_t s2u(const void* p) {
    uint32_t a;
    asm("{ .reg .u64 t; cvta.to.shared.u64 t, %1; cvt.u32.u64 %0, t; }" : "=r"(a) : "l"(p));
    return a;
}
__device__ __forceinline__ void cp16(void* smem, const void* g) {
    asm volatile("cp.async.cg.shared.global [%0], [%1], 16;"
                 :: "r"(s2u(smem)), "l"(g) : "memory");
}
__device__ __forceinline__ void cp_commit() {
    asm volatile("cp.async.commit_group;" ::: "memory");
}

__global__ void prep_kernel(const float* __restrict__ Wz,
                            const float* __restrict__ zw,
                            const float* __restrict__ zb)
{
    int t = threadIdx.x;
    for (int i = t; i < DZ*NHEAD; i += blockDim.x)
        g_wzp[i] = zw[i >> 4] * Wz[i];
    if (t < NHEAD) {
        float a = 0.f, b = 0.f;
        for (int c = 0; c < DZ; c++) {
            float wv = Wz[c*NHEAD + t];
            a += zw[c] * wv;
            b += zb[c] * wv;
        }
        g_alpha[t] = a;
        g_beta[t]  = b;
    }
}

__global__ __launch_bounds__(128) void ln_s_kernel(const float* __restrict__ s,
                                                   const float* __restrict__ w,
                                                   const float* __restrict__ b)
{
    __shared__ float sred[8];
    __shared__ float s_mu, s_rstd;
    int row = blockIdx.x, tid = threadIdx.x;
    float4 v = *(const float4*)&s[row*DMOD + tid*4];
    float sum = v.x + v.y + v.z + v.w;
    float ssq = v.x*v.x + v.y*v.y + v.z*v.z + v.w*v.w;
    #pragma unroll
    for (int o = 16; o; o >>= 1) {
        sum += __shfl_xor_sync(0xffffffffu, sum, o);
        ssq += __shfl_xor_sync(0xffffffffu, ssq, o);
    }
    int lane = tid & 31, wid = tid >> 5;
    if (lane == 0) { sred[wid] = sum; sred[4 + wid] = ssq; }
    __syncthreads();
    if (tid == 0) {
        float a = sred[0]+sred[1]+sred[2]+sred[3];
        float q = sred[4]+sred[5]+sred[6]+sred[7];
        float mu = a * (1.f/DMOD);
        float var = q * (1.f/DMOD) - mu*mu;
        s_mu = mu; s_rstd = rsqrtf(var + 1e-5f);
    }
    __syncthreads();
    float mu = s_mu, rstd = s_rstd;
    float4 wv = *(const float4*)&w[tid*4];
    float4 bv = *(const float4*)&b[tid*4];
    float o4[4];
    o4[0] = (v.x-mu)*rstd*wv.x + bv.x;
    o4[1] = (v.y-mu)*rstd*wv.y + bv.y;
    o4[2] = (v.z-mu)*rstd*wv.z + bv.z;
    o4[3] = (v.w-mu)*rstd*wv.w + bv.w;
    union { bf16 h[4]; uint2 u; } H, L;
    #pragma unroll
    for (int j = 0; j < 4; j++) {
        H.h[j] = __float2bfloat16(o4[j]);
        L.h[j] = __float2bfloat16(o4[j] - __bfloat162float(H.h[j]));
    }
    int idx = row*DMOD + tid*4;
    *(uint2*)&g_sa_hi[idx] = H.u;
    *(uint2*)&g_sa_lo[idx] = L.u;
}

__global__ void wtrans_kernel(const float* __restrict__ Wq, const float* __restrict__ Wk,
                              const float* __restrict__ Wv, const float* __restrict__ Wg,
                              const float* __restrict__ Wo)
{
    __shared__ float t[32][33];
    int g = blockIdx.z;
    const float* W = (g==0)?Wq:(g==1)?Wk:(g==2)?Wv:(g==3)?Wg:Wo;
    int tx = threadIdx.x, ty = threadIdx.y;
    int bx = blockIdx.x*32, by = blockIdx.y*32;
    #pragma unroll
    for (int i = 0; i < 4; i++)
        t[ty + 8*i][tx] = W[(size_t)(by + ty + 8*i)*DMOD + bx + tx];
    __syncthreads();
    size_t base = (size_t)g*DMOD*DMOD;
    #pragma unroll
    for (int i = 0; i < 4; i++) {
        int n = bx + ty + 8*i, k = by + tx;
        float v = t[tx][ty + 8*i];
        bf16 h = __float2bfloat16(v);
        g_wt_hi[base + (size_t)n*DMOD + k] = h;
        g_wt_lo[base + (size_t)n*DMOD + k] = __float2bfloat16(v - __bfloat162float(h));
    }
}

// WMMA bf16-split GEMM, 2-stage cp.async pipeline, 3-way split accumulators
// (hi*hi, hi*lo, lo*hi kept separate to break the HMMA RAW chain).
__global__ __launch_bounds__(256) void tc_gemm(const float* __restrict__ bq,
                                               float* __restrict__ Cout, int mode_sel)
{
    extern __shared__ __align__(16) char dynsm[];
    const int STAGE = 64*72*2;
    float* Cs = (float*)dynsm;

    int mode = (mode_sel < 0) ? (int)blockIdx.z : mode_sel;
    const bf16* Ah = (mode==4) ? g_oa_hi : g_sa_hi;
    const bf16* Al = (mode==4) ? g_oa_lo : g_sa_lo;
    size_t wb = (size_t)((mode==4)?4:mode)*DMOD*DMOD;
    const bf16* Bh = g_wt_hi + wb;
    const bf16* Bl = g_wt_lo + wb;

    int tid = threadIdx.x;
    int w = tid >> 5, wr = w >> 1, wc = w & 1;
    int m0 = blockIdx.y*64, n0 = blockIdx.x*64;
    int lrow = tid >> 2, lseg = (tid & 3) << 4;

    wmma::fragment<wmma::accumulator,16,16,16,float> accA[2], accB[2], accC[2];
    #pragma unroll
    for (int c = 0; c < 2; c++) {
        wmma::fill_fragment(accA[c], 0.f);
        wmma::fill_fragment(accB[c], 0.f);
        wmma::fill_fragment(accC[c], 0.f);
    }

    const bf16* gAh = Ah + (size_t)(m0+lrow)*DMOD + lseg;
    const bf16* gAl = Al + (size_t)(m0+lrow)*DMOD + lseg;
    const bf16* gBh = Bh + (size_t)(n0+lrow)*DMOD + lseg;
    const bf16* gBl = Bl + (size_t)(n0+lrow)*DMOD + lseg;
    int soff = (lrow*72 + lseg)*2;

    auto issue = [&](int ch, int st) {
        char* base = dynsm + st*4*STAGE;
        cp16(base + 0*STAGE + soff,      gAh + ch*64);
        cp16(base + 0*STAGE + soff + 16, gAh + ch*64 + 8);
        cp16(base + 1*STAGE + soff,      gAl + ch*64);
        cp16(base + 1*STAGE + soff + 16, gAl + ch*64 + 8);
        cp16(base + 2*STAGE + soff,      gBh + ch*64);
        cp16(base + 2*STAGE + soff + 16, gBh + ch*64 + 8);
        cp16(base + 3*STAGE + soff,      gBl + ch*64);
        cp16(base + 3*STAGE + soff + 16, gBl + ch*64 + 8);
        cp_commit();
    };

    issue(0, 0);
    for (int ch = 0; ch < 8; ch++) {
        int st = ch & 1;
        if (ch < 7) issue(ch+1, st^1);
        if (ch < 7) asm volatile("cp.async.wait_group 1;" ::: "memory");
        else        asm volatile("cp.async.wait_group 0;" ::: "memory");
        __syncthreads();
        bf16* Ah_s = (bf16*)(dynsm + st*4*STAGE + 0*STAGE);
        bf16* Al_s = (bf16*)(dynsm + st*4*STAGE + 1*STAGE);
        bf16* Bh_s = (bf16*)(dynsm + st*4*STAGE + 2*STAGE);
        bf16* Bl_s = (bf16*)(dynsm + st*4*STAGE + 3*STAGE);
        #pragma unroll
        for (int ks = 0; ks < 4; ks++) {
            wmma::fragment<wmma::matrix_a,16,16,16,bf16,wmma::row_major> fah, fal;
            wmma::load_matrix_sync(fah, Ah_s + (wr*16)*72 + ks*16, 72);
            wmma::load_matrix_sync(fal, Al_s + (wr*16)*72 + ks*16, 72);
            #pragma unroll
            for (int c = 0; c < 2; c++) {
                wmma::fragment<wmma::matrix_b,16,16,16,bf16,wmma::col_major> fbh, fbl;
                wmma::load_matrix_sync(fbh, Bh_s + (wc*32 + c*16)*72 + ks*16, 72);
                wmma::load_matrix_sync(fbl, Bl_s + (wc*32 + c*16)*72 + ks*16, 72);
                wmma::mma_sync(accA[c], fah, fbh, accA[c]);
                wmma::mma_sync(accB[c], fah, fbl, accB[c]);
                wmma::mma_sync(accC[c], fal, fbh, accC[c]);
            }
        }
        __syncthreads();
    }
    #pragma unroll
    for (int c = 0; c < 2; c++) {
        #pragma unroll
        for (int i = 0; i < accA[c].num_elements; i++)
            accA[c].x[i] += accB[c].x[i] + accC[c].x[i];
    }
    wmma::store_matrix_sync(Cs + (wr*16)*72 + wc*32,      accA[0], 72, wmma::mem_row_major);
    wmma::store_matrix_sync(Cs + (wr*16)*72 + wc*32 + 16, accA[1], 72, wmma::mem_row_major);
    __syncthreads();

    int r = lrow;
    int colg = n0 + lseg;
    if (mode <= 2) {
        bf16* dh = (mode==0) ? g_qh : (mode==1 ? g_kh : g_vh);
        bf16* dl = (mode==0) ? g_ql : (mode==1 ? g_kl : g_vl);
        size_t base = ((size_t)(colg >> 5)*NSEQ + m0 + r)*HDIM + (colg & 31);
        #pragma unroll
        for (int j = 0; j < 4; j++) {
            float4 v = *(float4*)&Cs[r*72 + lseg + j*4];
            if (mode == 0) {
                float4 bb = *(const float4*)&bq[colg + j*4];
                v.x = (v.x + bb.x)*QSCALE; v.y = (v.y + bb.y)*QSCALE;
                v.z = (v.z + bb.z)*QSCALE; v.w = (v.w + bb.w)*QSCALE;
            }
            float vr[4] = {v.x, v.y, v.z, v.w};
            union { bf16 h[4]; uint2 u; } H, L;
            #pragma unroll
            for (int e = 0; e < 4; e++) {
                H.h[e] = __float2bfloat16(vr[e]);
                L.h[e] = __float2bfloat16(vr[e] - __bfloat162float(H.h[e]));
            }
            *(uint2*)&dh[base + j*4] = H.u;
            *(uint2*)&dl[base + j*4] = L.u;
        }
    } else if (mode == 3) {
        float* dp = &g_gate[(size_t)(m0 + r)*DMOD + colg];
        #pragma unroll
        for (int j = 0; j < 4; j++) {
            float4 v = *(float4*)&Cs[r*72 + lseg + j*4];
            v.x = 1.f/(1.f + __expf(-v.x)); v.y = 1.f/(1.f + __expf(-v.y));
            v.z = 1.f/(1.f + __expf(-v.z)); v.w = 1.f/(1.f + __expf(-v.w));
            *(float4*)&dp[j*4] = v;
        }
    } else {
        float* dp = &Cout[(size_t)(m0 + r)*DMOD + colg];
        #pragma unroll
        for (int j = 0; j < 4; j++)
            *(float4*)&dp[j*4] = *(float4*)&Cs[r*72 + lseg + j*4];
    }
}

// fused LN(z)@Wz on tensor cores (R10 structure; split accumulators; fp16 out).
__global__ __launch_bounds__(256) void zbias_kernel(const float* __restrict__ z)
{
    __shared__ __align__(16) bf16 wzh[DZ][16];
    __shared__ __align__(16) bf16 wzl[DZ][16];
    __shared__ __align__(16) bf16 ztile[8][2][32][40];
    int tid = threadIdx.x, lane = tid & 31, w = tid >> 5;

    for (int i = tid; i < DZ*NHEAD; i += 256) {
        float v = g_wzp[i];
        bf16 h = __float2bfloat16(v);
        wzh[i >> 4][i & 15] = h;
        wzl[i >> 4][i & 15] = __float2bfloat16(v - __bfloat162float(h));
    }
    __syncthreads();

    int row0w = blockIdx.x*256 + w*32;
    const float* zwarp = z + (size_t)row0w*DZ;
    int lr8 = lane >> 3, lc8 = (lane & 7) << 2;

    wmma::fragment<wmma::accumulator,16,16,16,float> accA[2], accB[2], accC[2];
    #pragma unroll
    for (int rt = 0; rt < 2; rt++) {
        wmma::fill_fragment(accA[rt], 0.f);
        wmma::fill_fragment(accB[rt], 0.f);
        wmma::fill_fragment(accC[rt], 0.f);
    }
    float sumj[8], ssqj[8];
    #pragma unroll
    for (int j = 0; j < 8; j++) { sumj[j] = 0.f; ssqj[j] = 0.f; }

    bf16 (*zh)[40] = ztile[w][0];
    bf16 (*zl)[40] = ztile[w][1];

    float4 cur[8];
    #pragma unroll
    for (int j = 0; j < 8; j++)
        cur[j] = *(const float4*)&zwarp[(size_t)(j*4 + lr8)*DZ + lc8];

    for (int ch = 0; ch < 4; ch++) {
        #pragma unroll
        for (int j = 0; j < 8; j++) {
            float vr[4] = {cur[j].x, cur[j].y, cur[j].z, cur[j].w};
            union { bf16 h[4]; uint2 u; } H, L;
            #pragma unroll
            for (int e = 0; e < 4; e++) {
                H.h[e] = __float2bfloat16(vr[e]);
                L.h[e] = __float2bfloat16(vr[e] - __bfloat162float(H.h[e]));
                sumj[j] += vr[e];
                ssqj[j] = fmaf(vr[e], vr[e], ssqj[j]);
            }
            *(uint2*)&zh[j*4 + lr8][lc8] = H.u;
            *(uint2*)&zl[j*4 + lr8][lc8] = L.u;
        }
        __syncwarp();
        if (ch < 3) {
            #pragma unroll
            for (int j = 0; j < 8; j++)
                cur[j] = *(const float4*)&zwarp[(size_t)(j*4 + lr8)*DZ + (ch+1)*32 + lc8];
        }
        #pragma unroll
        for (int kt = 0; kt < 2; kt++) {
            wmma::fragment<wmma::matrix_b,16,16,16,bf16,wmma::row_major> fbh, fbl;
            wmma::load_matrix_sync(fbh, &wzh[ch*32 + kt*16][0], 16);
            wmma::load_matrix_sync(fbl, &wzl[ch*32 + kt*16][0], 16);
            #pragma unroll
            for (int rt = 0; rt < 2; rt++) {
                wmma::fragment<wmma::matrix_a,16,16,16,bf16,wmma::row_major> fah, fal;
                wmma::load_matrix_sync(fah, &zh[rt*16][kt*16], 40);
                wmma::load_matrix_sync(fal, &zl[rt*16][kt*16], 40);
                wmma::mma_sync(accA[rt], fah, fbh, accA[rt]);
                wmma::mma_sync(accB[rt], fah, fbl, accB[rt]);
                wmma::mma_sync(accC[rt], fal, fbh, accC[rt]);
            }
        }
        __syncwarp();
    }

    #pragma unroll
    for (int j = 0; j < 8; j++) {
        #pragma unroll
        for (int o = 1; o < 8; o <<= 1) {
            sumj[j] += __shfl_xor_sync(0xffffffffu, sumj[j], o);
            ssqj[j] += __shfl_xor_sync(0xffffffffu, ssqj[j], o);
        }
    }
    int srcLane = (lane & 3) * 8;
    float sum_own = 0.f, ssq_own = 0.f;
    #pragma unroll
    for (int j = 0; j < 8; j++) {
        float s_ = __shfl_sync(0xffffffffu, sumj[j], srcLane);
        float q_ = __shfl_sync(0xffffffffu, ssqj[j], srcLane);
        if ((lane >> 2) == j) { sum_own = s_; ssq_own = q_; }
    }

    #pragma unroll
    for (int rt = 0; rt < 2; rt++) {
        #pragma unroll
        for (int i = 0; i < accA[rt].num_elements; i++)
            accA[rt].x[i] += accB[rt].x[i] + accC[rt].x[i];
    }
    float* Cs = (float*)ztile[w];
    wmma::store_matrix_sync(Cs,          accA[0], 20, wmma::mem_row_major);
    wmma::store_matrix_sync(Cs + 16*20,  accA[1], 20, wmma::mem_row_major);
    __syncwarp();

    float mu = sum_own * (1.f/DZ);
    float var = ssq_own * (1.f/DZ) - mu*mu;
    float rstd = rsqrtf(var + 1e-5f);
    int row = row0w + lane;
    #pragma unroll
    for (int h = 0; h < NHEAD; h++) {
        float a = Cs[lane*20 + h];
        g_scoresh[(size_t)h*NN + row] =
            __float2half(rstd*(a - mu*g_alpha[h]) + g_beta[h]);
    }
}

// Flash attention v3: WMMA with 2-way split accumulators, fp16 zb bias,
// fused sigmoid-gating + bf16-split output epilogue.
__global__ __launch_bounds__(256) void flash_kernel()
{
    extern __shared__ __align__(16) char fsm[];
    bf16* Qh = (bf16*)fsm;                 // [64][40]
    bf16* Ql = Qh + 64*40;
    bf16* Kh = Ql + 64*40;
    bf16* Kl = Kh + 64*40;
    bf16* Vh = Kl + 64*40;
    bf16* Vl = Vh + 64*40;                 // 30720 B
    float* S  = (float*)(fsm + 30720);     // [64][72] fp32 (also PV partial)
    bf16* Ph = (bf16*)(fsm + 49152);       // [64][72]
    bf16* Pl = Ph + 64*72;                 // -> 67584
    float* Ob = (float*)(fsm + 67584);     // [64][36] -> 76800

    int tid = threadIdx.x, w = tid >> 5;
    int h = blockIdx.y, q0 = blockIdx.x*64;
    size_t hb = (size_t)h*NSEQ*HDIM;
    const __half* zp = g_scoresh + (size_t)h*NN;

    int row = tid >> 2;
    int seg8 = (tid & 3) << 3;
    *(uint4*)&Qh[row*40 + seg8] = *(const uint4*)&g_qh[hb + (size_t)(q0+row)*HDIM + seg8];
    *(uint4*)&Ql[row*40 + seg8] = *(const uint4*)&g_ql[hb + (size_t)(q0+row)*HDIM + seg8];
    for (int i = tid; i < 64*36; i += 256) Ob[i] = 0.f;

    float m = -1e30f, l = 0.f;
    int colb = (tid & 3) << 4;
    int oc = (tid & 3) << 3;

    for (int kb = 0; kb < NSEQ; kb += 64) {
        uint4 kh = *(const uint4*)&g_kh[hb + (size_t)(kb+row)*HDIM + seg8];
        uint4 kl = *(const uint4*)&g_kl[hb + (size_t)(kb+row)*HDIM + seg8];
        uint4 vh = *(const uint4*)&g_vh[hb + (size_t)(kb+row)*HDIM + seg8];
        uint4 vl = *(const uint4*)&g_vl[hb + (size_t)(kb+row)*HDIM + seg8];
        __syncthreads();
        *(uint4*)&Kh[row*40 + seg8] = kh;
        *(uint4*)&Kl[row*40 + seg8] = kl;
        *(uint4*)&Vh[row*40 + seg8] = vh;
        *(uint4*)&Vl[row*40 + seg8] = vl;
        __syncthreads();

        {
            int mr = w >> 1;
            wmma::fragment<wmma::accumulator,16,16,16,float> saA[2], saB[2];
            #pragma unroll
            for (int c = 0; c < 2; c++) {
                wmma::fill_fragment(saA[c], 0.f);
                wmma::fill_fragment(saB[c], 0.f);
            }
            #pragma unroll
            for (int ks = 0; ks < 2; ks++) {
                wmma::fragment<wmma::matrix_a,16,16,16,bf16,wmma::row_major> qhf, qlf;
                wmma::load_matrix_sync(qhf, Qh + (mr*16)*40 + ks*16, 40);
                wmma::load_matrix_sync(qlf, Ql + (mr*16)*40 + ks*16, 40);
                #pragma unroll
                for (int c = 0; c < 2; c++) {
                    int nc = (w & 1) + c*2;
                    wmma::fragment<wmma::matrix_b,16,16,16,bf16,wmma::col_major> kbh, kbl;
                    wmma::load_matrix_sync(kbh, Kh + (nc*16)*40 + ks*16, 40);
                    wmma::load_matrix_sync(kbl, Kl + (nc*16)*40 + ks*16, 40);
                    wmma::mma_sync(saA[c], qhf, kbh, saA[c]);
                    wmma::mma_sync(saB[c], qhf, kbl, saB[c]);
                    wmma::mma_sync(saB[c], qlf, kbh, saB[c]);
                }
            }
            #pragma unroll
            for (int c = 0; c < 2; c++) {
                #pragma unroll
                for (int i = 0; i < saA[c].num_elements; i++)
                    saA[c].x[i] += saB[c].x[i];
            }
            wmma::store_matrix_sync(S + ((w>>1)*16)*72 + (w&1)*16,     saA[0], 72, wmma::mem_row_major);
            wmma::store_matrix_sync(S + ((w>>1)*16)*72 + ((w&1)+2)*16, saA[1], 72, wmma::mem_row_major);
        }
        __syncthreads();

        float sv[16];
        {
            union { __half hh[8]; uint4 u; } Z0, Z1;
            Z0.u = *(const uint4*)&zp[(size_t)(q0+row)*NSEQ + kb + colb];
            Z1.u = *(const uint4*)&zp[(size_t)(q0+row)*NSEQ + kb + colb + 8];
            #pragma unroll
            for (int j = 0; j < 8; j++) {
                sv[j]   = S[row*72 + colb + j]     + __half2float(Z0.hh[j]);
                sv[8+j] = S[row*72 + colb + 8 + j] + __half2float(Z1.hh[j]);
            }
        }
        float mx = sv[0];
        #pragma unroll
        for (int j = 1; j < 16; j++) mx = fmaxf(mx, sv[j]);
        mx = fmaxf(mx, __shfl_xor_sync(0xffffffffu, mx, 1));
        mx = fmaxf(mx, __shfl_xor_sync(0xffffffffu, mx, 2));
        float mnew = fmaxf(m, mx);
        float c = __expf(m - mnew);
        float rs = 0.f;
        union { bf16 h[8]; uint4 u; } PH[2], PL[2];
        #pragma unroll
        for (int j = 0; j < 16; j++) {
            float e = __expf(sv[j] - mnew);
            rs += e;
            bf16 eh = __float2bfloat16(e);
            PH[j>>3].h[j&7] = eh;
            PL[j>>3].h[j&7] = __float2bfloat16(e - __bfloat162float(eh));
        }
        rs += __shfl_xor_sync(0xffffffffu, rs, 1);
        rs += __shfl_xor_sync(0xffffffffu, rs, 2);
        l = l*c + rs;
        m = mnew;
        *(uint4*)&Ph[row*72 + colb]     = PH[0].u;
        *(uint4*)&Ph[row*72 + colb + 8] = PH[1].u;
        *(uint4*)&Pl[row*72 + colb]     = PL[0].u;
        *(uint4*)&Pl[row*72 + colb + 8] = PL[1].u;
        __syncthreads();

        {
            int mr = w >> 1, nc = w & 1;
            wmma::fragment<wmma::accumulator,16,16,16,float> oaA, oaB;
            wmma::fill_fragment(oaA, 0.f);
            wmma::fill_fragment(oaB, 0.f);
            #pragma unroll
            for (int ks = 0; ks < 4; ks++) {
                wmma::fragment<wmma::matrix_a,16,16,16,bf16,wmma::row_major> phf, plf;
                wmma::load_matrix_sync(phf, Ph + (mr*16)*72 + ks*16, 72);
                wmma::load_matrix_sync(plf, Pl + (mr*16)*72 + ks*16, 72);
                wmma::fragment<wmma::matrix_b,16,16,16,bf16,wmma::row_major> vbh, vbl;
                wmma::load_matrix_sync(vbh, Vh + (ks*16)*40 + nc*16, 40);
                wmma::load_matrix_sync(vbl, Vl + (ks*16)*40 + nc*16, 40);
                wmma::mma_sync(oaA, phf, vbh, oaA);
                wmma::mma_sync(oaB, phf, vbl, oaB);
                wmma::mma_sync(oaB, plf, vbh, oaB);
            }
            #pragma unroll
            for (int i = 0; i < oaA.num_elements; i++)
                oaA.x[i] += oaB.x[i];
            wmma::store_matrix_sync(S + (mr*16)*72 + nc*16, oaA, 72, wmma::mem_row_major);
        }
        __syncthreads();

        #pragma unroll
        for (int j = 0; j < 2; j++) {
            float4 p = *(float4*)&S[row*72 + oc + j*4];
            float4 o = *(float4*)&Ob[row*36 + oc + j*4];
            o.x = o.x*c + p.x; o.y = o.y*c + p.y;
            o.z = o.z*c + p.z; o.w = o.w*c + p.w;
            *(float4*)&Ob[row*36 + oc + j*4] = o;
        }
    }

    // epilogue: o = (O/l) * gate; split to bf16 hi/lo for the out-projection
    float inv = 1.f / l;
    size_t obase = (size_t)(q0+row)*DMOD + h*HDIM + oc;
    #pragma unroll
    for (int j = 0; j < 2; j++) {
        float4 o = *(float4*)&Ob[row*36 + oc + j*4];
        float4 g = *(const float4*)&g_gate[obase + j*4];
        float vr[4] = {o.x*inv*g.x, o.y*inv*g.y, o.z*inv*g.z, o.w*inv*g.w};
        union { bf16 h[4]; uint2 u; } H, L;
        #pragma unroll
        for (int e = 0; e < 4; e++) {
            H.h[e] = __float2bfloat16(vr[e]);
            L.h[e] = __float2bfloat16(vr[e] - __bfloat162float(H.h[e]));
        }
        *(uint2*)&g_oa_hi[obase + j*4] = H.u;
        *(uint2*)&g_oa_lo[obase + j*4] = L.u;
    }
}

extern "C" void kernel_launch(void* const* d_in, const int* in_sizes, int n_in,
                              void* d_out, int out_size)
{
    const float* s   = (const float*)d_in[0];
    const float* z   = (const float*)d_in[1];
    const float* nsw = (const float*)d_in[2];
    const float* nsb = (const float*)d_in[3];
    const float* Wq  = (const float*)d_in[4];
    const float* bq  = (const float*)d_in[5];
    const float* Wk  = (const float*)d_in[6];
    const float* Wv  = (const float*)d_in[7];
    const float* Wg  = (const float*)d_in[8];
    const float* zw  = (const float*)d_in[9];
    const float* zb  = (const float*)d_in[10];
    const float* Wz  = (const float*)d_in[11];
    const float* Wo  = (const float*)d_in[12];
    float* out = (float*)d_out;

    cudaFuncSetAttribute(tc_gemm, cudaFuncAttributeMaxDynamicSharedMemorySize, 73728);
    cudaFuncSetAttribute(flash_kernel, cudaFuncAttributeMaxDynamicSharedMemorySize, 76800);

    prep_kernel<<<1, 256>>>(Wz, zw, zb);
    ln_s_kernel<<<NSEQ, 128>>>(s, nsw, nsb);
    wtrans_kernel<<<dim3(16,16,5), dim3(32,8)>>>(Wq, Wk, Wv, Wg, Wo);
    tc_gemm<<<dim3(8,16,4), 256, 73728>>>(bq, nullptr, -1);
    zbias_kernel<<<NN/256, 256>>>(z);
    flash_kernel<<<dim3(NSEQ/64, NHEAD), 256, 76800>>>();
    tc_gemm<<<dim3(8,16,1), 256, 73728>>>(bq, out, 4);
}

// round 14
// speedup vs baseline: 1.0084x; 1.0084x over previous
#include <cuda_runtime.h>
#include <cuda_bf16.h>
#include <cuda_fp16.h>
#include <mma.h>
#include <math.h>
#include <stdint.h>

using namespace nvcuda;

#define NSEQ 1024
#define DMOD 512
#define NHEAD 16
#define HDIM 32
#define DZ 128
#define NN (NSEQ*NSEQ)
#define QSCALE 0.17677669529663687f

typedef unsigned long long u64;
typedef __nv_bfloat16 bf16;

__device__ float g_gate[NSEQ*DMOD];
__device__ __half g_scoresh[NHEAD*NN];
__device__ float g_wzp[DZ*NHEAD];
__device__ float g_alpha[NHEAD];
__device__ float g_beta[NHEAD];
__device__ bf16 g_sa_hi[NSEQ*DMOD], g_sa_lo[NSEQ*DMOD];
__device__ bf16 g_oa_hi[NSEQ*DMOD], g_oa_lo[NSEQ*DMOD];
__device__ bf16 g_wt_hi[5*DMOD*DMOD], g_wt_lo[5*DMOD*DMOD];
__device__ bf16 g_qh[NHEAD*NSEQ*HDIM], g_ql[NHEAD*NSEQ*HDIM];
__device__ bf16 g_kh[NHEAD*NSEQ*HDIM], g_kl[NHEAD*NSEQ*HDIM];
__device__ bf16 g_vh[NHEAD*NSEQ*HDIM], g_vl[NHEAD*NSEQ*HDIM];

__device__ __forceinline__ uint32_t s2u(const void* p) {
    uint32_t a;
    asm("{ .reg .u64 t; cvta.to.shared.u64 t, %1; cvt.u32.u64 %0, t; }" : "=r"(a) : "l"(p));
    return a;
}
__device__ __forceinline__ void cp16(void* smem, const void* g) {
    asm volatile("cp.async.cg.shared.global [%0], [%1], 16;"
                 :: "r"(s2u(smem)), "l"(g) : "memory");
}
__device__ __forceinline__ void cp_commit() {
    asm volatile("cp.async.commit_group;" ::: "memory");
}

__global__ void prep_kernel(const float* __restrict__ Wz,
                            const float* __restrict__ zw,
                            const float* __restrict__ zb)
{
    int t = threadIdx.x;
    for (int i = t; i < DZ*NHEAD; i += blockDim.x)
        g_wzp[i] = zw[i >> 4] * Wz[i];
    if (t < NHEAD) {
        float a = 0.f, b = 0.f;
        for (int c = 0; c < DZ; c++) {
            float wv = Wz[c*NHEAD + t];
            a += zw[c] * wv;
            b += zb[c] * wv;
        }
        g_alpha[t] = a;
        g_beta[t]  = b;
    }
}

__global__ __launch_bounds__(128) void ln_s_kernel(const float* __restrict__ s,
                                                   const float* __restrict__ w,
                                                   const float* __restrict__ b)
{
    __shared__ float sred[8];
    __shared__ float s_mu, s_rstd;
    int row = blockIdx.x, tid = threadIdx.x;
    float4 v = *(const float4*)&s[row*DMOD + tid*4];
    float sum = v.x + v.y + v.z + v.w;
    float ssq = v.x*v.x + v.y*v.y + v.z*v.z + v.w*v.w;
    #pragma unroll
    for (int o = 16; o; o >>= 1) {
        sum += __shfl_xor_sync(0xffffffffu, sum, o);
        ssq += __shfl_xor_sync(0xffffffffu, ssq, o);
    }
    int lane = tid & 31, wid = tid >> 5;
    if (lane == 0) { sred[wid] = sum; sred[4 + wid] = ssq; }
    __syncthreads();
    if (tid == 0) {
        float a = sred[0]+sred[1]+sred[2]+sred[3];
        float q = sred[4]+sred[5]+sred[6]+sred[7];
        float mu = a * (1.f/DMOD);
        float var = q * (1.f/DMOD) - mu*mu;
        s_mu = mu; s_rstd = rsqrtf(var + 1e-5f);
    }
    __syncthreads();
    float mu = s_mu, rstd = s_rstd;
    float4 wv = *(const float4*)&w[tid*4];
    float4 bv = *(const float4*)&b[tid*4];
    float o4[4];
    o4[0] = (v.x-mu)*rstd*wv.x + bv.x;
    o4[1] = (v.y-mu)*rstd*wv.y + bv.y;
    o4[2] = (v.z-mu)*rstd*wv.z + bv.z;
    o4[3] = (v.w-mu)*rstd*wv.w + bv.w;
    union { bf16 h[4]; uint2 u; } H, L;
    #pragma unroll
    for (int j = 0; j < 4; j++) {
        H.h[j] = __float2bfloat16(o4[j]);
        L.h[j] = __float2bfloat16(o4[j] - __bfloat162float(H.h[j]));
    }
    int idx = row*DMOD + tid*4;
    *(uint2*)&g_sa_hi[idx] = H.u;
    *(uint2*)&g_sa_lo[idx] = L.u;
}

__global__ void wtrans_kernel(const float* __restrict__ Wq, const float* __restrict__ Wk,
                              const float* __restrict__ Wv, const float* __restrict__ Wg,
                              const float* __restrict__ Wo)
{
    __shared__ float t[32][33];
    int g = blockIdx.z;
    const float* W = (g==0)?Wq:(g==1)?Wk:(g==2)?Wv:(g==3)?Wg:Wo;
    int tx = threadIdx.x, ty = threadIdx.y;
    int bx = blockIdx.x*32, by = blockIdx.y*32;
    #pragma unroll
    for (int i = 0; i < 4; i++)
        t[ty + 8*i][tx] = W[(size_t)(by + ty + 8*i)*DMOD + bx + tx];
    __syncthreads();
    size_t base = (size_t)g*DMOD*DMOD;
    #pragma unroll
    for (int i = 0; i < 4; i++) {
        int n = bx + ty + 8*i, k = by + tx;
        float v = t[tx][ty + 8*i];
        bf16 h = __float2bfloat16(v);
        g_wt_hi[base + (size_t)n*DMOD + k] = h;
        g_wt_lo[base + (size_t)n*DMOD + k] = __float2bfloat16(v - __bfloat162float(h));
    }
}

// WMMA bf16-split GEMM, 2-stage cp.async pipeline, 3-way split accumulators.
__global__ __launch_bounds__(256) void tc_gemm(const float* __restrict__ bq,
                                               float* __restrict__ Cout, int mode_sel)
{
    extern __shared__ __align__(16) char dynsm[];
    const int STAGE = 64*72*2;
    float* Cs = (float*)dynsm;

    int mode = (mode_sel < 0) ? (int)blockIdx.z : mode_sel;
    const bf16* Ah = (mode==4) ? g_oa_hi : g_sa_hi;
    const bf16* Al = (mode==4) ? g_oa_lo : g_sa_lo;
    size_t wb = (size_t)((mode==4)?4:mode)*DMOD*DMOD;
    const bf16* Bh = g_wt_hi + wb;
    const bf16* Bl = g_wt_lo + wb;

    int tid = threadIdx.x;
    int w = tid >> 5, wr = w >> 1, wc = w & 1;
    int m0 = blockIdx.y*64, n0 = blockIdx.x*64;
    int lrow = tid >> 2, lseg = (tid & 3) << 4;

    wmma::fragment<wmma::accumulator,16,16,16,float> accA[2], accB[2], accC[2];
    #pragma unroll
    for (int c = 0; c < 2; c++) {
        wmma::fill_fragment(accA[c], 0.f);
        wmma::fill_fragment(accB[c], 0.f);
        wmma::fill_fragment(accC[c], 0.f);
    }

    const bf16* gAh = Ah + (size_t)(m0+lrow)*DMOD + lseg;
    const bf16* gAl = Al + (size_t)(m0+lrow)*DMOD + lseg;
    const bf16* gBh = Bh + (size_t)(n0+lrow)*DMOD + lseg;
    const bf16* gBl = Bl + (size_t)(n0+lrow)*DMOD + lseg;
    int soff = (lrow*72 + lseg)*2;

    auto issue = [&](int ch, int st) {
        char* base = dynsm + st*4*STAGE;
        cp16(base + 0*STAGE + soff,      gAh + ch*64);
        cp16(base + 0*STAGE + soff + 16, gAh + ch*64 + 8);
        cp16(base + 1*STAGE + soff,      gAl + ch*64);
        cp16(base + 1*STAGE + soff + 16, gAl + ch*64 + 8);
        cp16(base + 2*STAGE + soff,      gBh + ch*64);
        cp16(base + 2*STAGE + soff + 16, gBh + ch*64 + 8);
        cp16(base + 3*STAGE + soff,      gBl + ch*64);
        cp16(base + 3*STAGE + soff + 16, gBl + ch*64 + 8);
        cp_commit();
    };

    issue(0, 0);
    for (int ch = 0; ch < 8; ch++) {
        int st = ch & 1;
        if (ch < 7) issue(ch+1, st^1);
        if (ch < 7) asm volatile("cp.async.wait_group 1;" ::: "memory");
        else        asm volatile("cp.async.wait_group 0;" ::: "memory");
        __syncthreads();
        bf16* Ah_s = (bf16*)(dynsm + st*4*STAGE + 0*STAGE);
        bf16* Al_s = (bf16*)(dynsm + st*4*STAGE + 1*STAGE);
        bf16* Bh_s = (bf16*)(dynsm + st*4*STAGE + 2*STAGE);
        bf16* Bl_s = (bf16*)(dynsm + st*4*STAGE + 3*STAGE);
        #pragma unroll
        for (int ks = 0; ks < 4; ks++) {
            wmma::fragment<wmma::matrix_a,16,16,16,bf16,wmma::row_major> fah, fal;
            wmma::load_matrix_sync(fah, Ah_s + (wr*16)*72 + ks*16, 72);
            wmma::load_matrix_sync(fal, Al_s + (wr*16)*72 + ks*16, 72);
            #pragma unroll
            for (int c = 0; c < 2; c++) {
                wmma::fragment<wmma::matrix_b,16,16,16,bf16,wmma::col_major> fbh, fbl;
                wmma::load_matrix_sync(fbh, Bh_s + (wc*32 + c*16)*72 + ks*16, 72);
                wmma::load_matrix_sync(fbl, Bl_s + (wc*32 + c*16)*72 + ks*16, 72);
                wmma::mma_sync(accA[c], fah, fbh, accA[c]);
                wmma::mma_sync(accB[c], fah, fbl, accB[c]);
                wmma::mma_sync(accC[c], fal, fbh, accC[c]);
            }
        }
        __syncthreads();
    }
    #pragma unroll
    for (int c = 0; c < 2; c++) {
        #pragma unroll
        for (int i = 0; i < accA[c].num_elements; i++)
            accA[c].x[i] += accB[c].x[i] + accC[c].x[i];
    }
    wmma::store_matrix_sync(Cs + (wr*16)*72 + wc*32,      accA[0], 72, wmma::mem_row_major);
    wmma::store_matrix_sync(Cs + (wr*16)*72 + wc*32 + 16, accA[1], 72, wmma::mem_row_major);
    __syncthreads();

    int r = lrow;
    int colg = n0 + lseg;
    if (mode <= 2) {
        bf16* dh = (mode==0) ? g_qh : (mode==1 ? g_kh : g_vh);
        bf16* dl = (mode==0) ? g_ql : (mode==1 ? g_kl : g_vl);
        size_t base = ((size_t)(colg >> 5)*NSEQ + m0 + r)*HDIM + (colg & 31);
        #pragma unroll
        for (int j = 0; j < 4; j++) {
            float4 v = *(float4*)&Cs[r*72 + lseg + j*4];
            if (mode == 0) {
                float4 bb = *(const float4*)&bq[colg + j*4];
                v.x = (v.x + bb.x)*QSCALE; v.y = (v.y + bb.y)*QSCALE;
                v.z = (v.z + bb.z)*QSCALE; v.w = (v.w + bb.w)*QSCALE;
            }
            float vr[4] = {v.x, v.y, v.z, v.w};
            union { bf16 h[4]; uint2 u; } H, L;
            #pragma unroll
            for (int e = 0; e < 4; e++) {
                H.h[e] = __float2bfloat16(vr[e]);
                L.h[e] = __float2bfloat16(vr[e] - __bfloat162float(H.h[e]));
            }
            *(uint2*)&dh[base + j*4] = H.u;
            *(uint2*)&dl[base + j*4] = L.u;
        }
    } else if (mode == 3) {
        float* dp = &g_gate[(size_t)(m0 + r)*DMOD + colg];
        #pragma unroll
        for (int j = 0; j < 4; j++) {
            float4 v = *(float4*)&Cs[r*72 + lseg + j*4];
            v.x = 1.f/(1.f + __expf(-v.x)); v.y = 1.f/(1.f + __expf(-v.y));
            v.z = 1.f/(1.f + __expf(-v.z)); v.w = 1.f/(1.f + __expf(-v.w));
            *(float4*)&dp[j*4] = v;
        }
    } else {
        float* dp = &Cout[(size_t)(m0 + r)*DMOD + colg];
        #pragma unroll
        for (int j = 0; j < 4; j++)
            *(float4*)&dp[j*4] = *(float4*)&Cs[r*72 + lseg + j*4];
    }
}

// fused LN(z)@Wz on tensor cores (R13, unchanged: split accs, fp16 out).
__global__ __launch_bounds__(256) void zbias_kernel(const float* __restrict__ z)
{
    __shared__ __align__(16) bf16 wzh[DZ][16];
    __shared__ __align__(16) bf16 wzl[DZ][16];
    __shared__ __align__(16) bf16 ztile[8][2][32][40];
    int tid = threadIdx.x, lane = tid & 31, w = tid >> 5;

    for (int i = tid; i < DZ*NHEAD; i += 256) {
        float v = g_wzp[i];
        bf16 h = __float2bfloat16(v);
        wzh[i >> 4][i & 15] = h;
        wzl[i >> 4][i & 15] = __float2bfloat16(v - __bfloat162float(h));
    }
    __syncthreads();

    int row0w = blockIdx.x*256 + w*32;
    const float* zwarp = z + (size_t)row0w*DZ;
    int lr8 = lane >> 3, lc8 = (lane & 7) << 2;

    wmma::fragment<wmma::accumulator,16,16,16,float> accA[2], accB[2], accC[2];
    #pragma unroll
    for (int rt = 0; rt < 2; rt++) {
        wmma::fill_fragment(accA[rt], 0.f);
        wmma::fill_fragment(accB[rt], 0.f);
        wmma::fill_fragment(accC[rt], 0.f);
    }
    float sumj[8], ssqj[8];
    #pragma unroll
    for (int j = 0; j < 8; j++) { sumj[j] = 0.f; ssqj[j] = 0.f; }

    bf16 (*zh)[40] = ztile[w][0];
    bf16 (*zl)[40] = ztile[w][1];

    float4 cur[8];
    #pragma unroll
    for (int j = 0; j < 8; j++)
        cur[j] = *(const float4*)&zwarp[(size_t)(j*4 + lr8)*DZ + lc8];

    for (int ch = 0; ch < 4; ch++) {
        #pragma unroll
        for (int j = 0; j < 8; j++) {
            float vr[4] = {cur[j].x, cur[j].y, cur[j].z, cur[j].w};
            union { bf16 h[4]; uint2 u; } H, L;
            #pragma unroll
            for (int e = 0; e < 4; e++) {
                H.h[e] = __float2bfloat16(vr[e]);
                L.h[e] = __float2bfloat16(vr[e] - __bfloat162float(H.h[e]));
                sumj[j] += vr[e];
                ssqj[j] = fmaf(vr[e], vr[e], ssqj[j]);
            }
            *(uint2*)&zh[j*4 + lr8][lc8] = H.u;
            *(uint2*)&zl[j*4 + lr8][lc8] = L.u;
        }
        __syncwarp();
        if (ch < 3) {
            #pragma unroll
            for (int j = 0; j < 8; j++)
                cur[j] = *(const float4*)&zwarp[(size_t)(j*4 + lr8)*DZ + (ch+1)*32 + lc8];
        }
        #pragma unroll
        for (int kt = 0; kt < 2; kt++) {
            wmma::fragment<wmma::matrix_b,16,16,16,bf16,wmma::row_major> fbh, fbl;
            wmma::load_matrix_sync(fbh, &wzh[ch*32 + kt*16][0], 16);
            wmma::load_matrix_sync(fbl, &wzl[ch*32 + kt*16][0], 16);
            #pragma unroll
            for (int rt = 0; rt < 2; rt++) {
                wmma::fragment<wmma::matrix_a,16,16,16,bf16,wmma::row_major> fah, fal;
                wmma::load_matrix_sync(fah, &zh[rt*16][kt*16], 40);
                wmma::load_matrix_sync(fal, &zl[rt*16][kt*16], 40);
                wmma::mma_sync(accA[rt], fah, fbh, accA[rt]);
                wmma::mma_sync(accB[rt], fah, fbl, accB[rt]);
                wmma::mma_sync(accC[rt], fal, fbh, accC[rt]);
            }
        }
        __syncwarp();
    }

    #pragma unroll
    for (int j = 0; j < 8; j++) {
        #pragma unroll
        for (int o = 1; o < 8; o <<= 1) {
            sumj[j] += __shfl_xor_sync(0xffffffffu, sumj[j], o);
            ssqj[j] += __shfl_xor_sync(0xffffffffu, ssqj[j], o);
        }
    }
    int srcLane = (lane & 3) * 8;
    float sum_own = 0.f, ssq_own = 0.f;
    #pragma unroll
    for (int j = 0; j < 8; j++) {
        float s_ = __shfl_sync(0xffffffffu, sumj[j], srcLane);
        float q_ = __shfl_sync(0xffffffffu, ssqj[j], srcLane);
        if ((lane >> 2) == j) { sum_own = s_; ssq_own = q_; }
    }

    #pragma unroll
    for (int rt = 0; rt < 2; rt++) {
        #pragma unroll
        for (int i = 0; i < accA[rt].num_elements; i++)
            accA[rt].x[i] += accB[rt].x[i] + accC[rt].x[i];
    }
    float* Cs = (float*)ztile[w];
    wmma::store_matrix_sync(Cs,          accA[0], 20, wmma::mem_row_major);
    wmma::store_matrix_sync(Cs + 16*20,  accA[1], 20, wmma::mem_row_major);
    __syncwarp();

    float mu = sum_own * (1.f/DZ);
    float var = ssq_own * (1.f/DZ) - mu*mu;
    float rstd = rsqrtf(var + 1e-5f);
    int row = row0w + lane;
    #pragma unroll
    for (int h = 0; h < NHEAD; h++) {
        float a = Cs[lane*20 + h];
        g_scoresh[(size_t)h*NN + row] =
            __float2half(rstd*(a - mu*g_alpha[h]) + g_beta[h]);
    }
}

// Flash attention v4: chained accumulators (register-lean, R12 structure),
// fp16 zb bias, fused sigmoid-gating epilogue, occupancy pinned to 2 CTA/SM.
__global__ void __launch_bounds__(256, 2) flash_kernel()
{
    extern __shared__ __align__(16) char fsm[];
    bf16* Qh = (bf16*)fsm;                 // [64][40]
    bf16* Ql = Qh + 64*40;
    bf16* Kh = Ql + 64*40;
    bf16* Kl = Kh + 64*40;
    bf16* Vh = Kl + 64*40;
    bf16* Vl = Vh + 64*40;                 // 30720 B
    float* S  = (float*)(fsm + 30720);     // [64][72] fp32 (also PV partial)
    bf16* Ph = (bf16*)(fsm + 49152);       // [64][72]
    bf16* Pl = Ph + 64*72;                 // -> 67584
    float* Ob = (float*)(fsm + 67584);     // [64][36] -> 76800

    int tid = threadIdx.x, w = tid >> 5;
    int h = blockIdx.y, q0 = blockIdx.x*64;
    size_t hb = (size_t)h*NSEQ*HDIM;
    const __half* zp = g_scoresh + (size_t)h*NN;

    int row = tid >> 2;
    int seg8 = (tid & 3) << 3;
    *(uint4*)&Qh[row*40 + seg8] = *(const uint4*)&g_qh[hb + (size_t)(q0+row)*HDIM + seg8];
    *(uint4*)&Ql[row*40 + seg8] = *(const uint4*)&g_ql[hb + (size_t)(q0+row)*HDIM + seg8];
    for (int i = tid; i < 64*36; i += 256) Ob[i] = 0.f;

    float m = -1e30f, l = 0.f;
    int colb = (tid & 3) << 4;
    int oc = (tid & 3) << 3;

    for (int kb = 0; kb < NSEQ; kb += 64) {
        uint4 kh = *(const uint4*)&g_kh[hb + (size_t)(kb+row)*HDIM + seg8];
        uint4 kl = *(const uint4*)&g_kl[hb + (size_t)(kb+row)*HDIM + seg8];
        uint4 vh = *(const uint4*)&g_vh[hb + (size_t)(kb+row)*HDIM + seg8];
        uint4 vl = *(const uint4*)&g_vl[hb + (size_t)(kb+row)*HDIM + seg8];
        __syncthreads();
        *(uint4*)&Kh[row*40 + seg8] = kh;
        *(uint4*)&Kl[row*40 + seg8] = kl;
        *(uint4*)&Vh[row*40 + seg8] = vh;
        *(uint4*)&Vl[row*40 + seg8] = vl;
        __syncthreads();

        {
            int mr = w >> 1;
            wmma::fragment<wmma::accumulator,16,16,16,float> sa[2];
            wmma::fill_fragment(sa[0], 0.f);
            wmma::fill_fragment(sa[1], 0.f);
            #pragma unroll
            for (int ks = 0; ks < 2; ks++) {
                wmma::fragment<wmma::matrix_a,16,16,16,bf16,wmma::row_major> qhf, qlf;
                wmma::load_matrix_sync(qhf, Qh + (mr*16)*40 + ks*16, 40);
                wmma::load_matrix_sync(qlf, Ql + (mr*16)*40 + ks*16, 40);
                #pragma unroll
                for (int c = 0; c < 2; c++) {
                    int nc = (w & 1) + c*2;
                    wmma::fragment<wmma::matrix_b,16,16,16,bf16,wmma::col_major> kbh, kbl;
                    wmma::load_matrix_sync(kbh, Kh + (nc*16)*40 + ks*16, 40);
                    wmma::load_matrix_sync(kbl, Kl + (nc*16)*40 + ks*16, 40);
                    wmma::mma_sync(sa[c], qhf, kbh, sa[c]);
                    wmma::mma_sync(sa[c], qhf, kbl, sa[c]);
                    wmma::mma_sync(sa[c], qlf, kbh, sa[c]);
                }
            }
            wmma::store_matrix_sync(S + (mr*16)*72 + (w&1)*16,     sa[0], 72, wmma::mem_row_major);
            wmma::store_matrix_sync(S + (mr*16)*72 + ((w&1)+2)*16, sa[1], 72, wmma::mem_row_major);
        }
        __syncthreads();

        float sv[16];
        {
            union { __half hh[8]; uint4 u; } Z0, Z1;
            Z0.u = *(const uint4*)&zp[(size_t)(q0+row)*NSEQ + kb + colb];
            Z1.u = *(const uint4*)&zp[(size_t)(q0+row)*NSEQ + kb + colb + 8];
            #pragma unroll
            for (int j = 0; j < 8; j++) {
                sv[j]   = S[row*72 + colb + j]     + __half2float(Z0.hh[j]);
                sv[8+j] = S[row*72 + colb + 8 + j] + __half2float(Z1.hh[j]);
            }
        }
        float mx = sv[0];
        #pragma unroll
        for (int j = 1; j < 16; j++) mx = fmaxf(mx, sv[j]);
        mx = fmaxf(mx, __shfl_xor_sync(0xffffffffu, mx, 1));
        mx = fmaxf(mx, __shfl_xor_sync(0xffffffffu, mx, 2));
        float mnew = fmaxf(m, mx);
        float c = __expf(m - mnew);
        float rs = 0.f;
        union { bf16 h[8]; uint4 u; } PH[2], PL[2];
        #pragma unroll
        for (int j = 0; j < 16; j++) {
            float e = __expf(sv[j] - mnew);
            rs += e;
            bf16 eh = __float2bfloat16(e);
            PH[j>>3].h[j&7] = eh;
            PL[j>>3].h[j&7] = __float2bfloat16(e - __bfloat162float(eh));
        }
        rs += __shfl_xor_sync(0xffffffffu, rs, 1);
        rs += __shfl_xor_sync(0xffffffffu, rs, 2);
        l = l*c + rs;
        m = mnew;
        *(uint4*)&Ph[row*72 + colb]     = PH[0].u;
        *(uint4*)&Ph[row*72 + colb + 8] = PH[1].u;
        *(uint4*)&Pl[row*72 + colb]     = PL[0].u;
        *(uint4*)&Pl[row*72 + colb + 8] = PL[1].u;
        __syncthreads();

        {
            int mr = w >> 1, nc = w & 1;
            wmma::fragment<wmma::accumulator,16,16,16,float> oa;
            wmma::fill_fragment(oa, 0.f);
            #pragma unroll
            for (int ks = 0; ks < 4; ks++) {
                wmma::fragment<wmma::matrix_a,16,16,16,bf16,wmma::row_major> phf, plf;
                wmma::load_matrix_sync(phf, Ph + (mr*16)*72 + ks*16, 72);
                wmma::load_matrix_sync(plf, Pl + (mr*16)*72 + ks*16, 72);
                wmma::fragment<wmma::matrix_b,16,16,16,bf16,wmma::row_major> vbh, vbl;
                wmma::load_matrix_sync(vbh, Vh + (ks*16)*40 + nc*16, 40);
                wmma::load_matrix_sync(vbl, Vl + (ks*16)*40 + nc*16, 40);
                wmma::mma_sync(oa, phf, vbh, oa);
                wmma::mma_sync(oa, phf, vbl, oa);
                wmma::mma_sync(oa, plf, vbh, oa);
            }
            wmma::store_matrix_sync(S + (mr*16)*72 + nc*16, oa, 72, wmma::mem_row_major);
        }
        __syncthreads();

        #pragma unroll
        for (int j = 0; j < 2; j++) {
            float4 p = *(float4*)&S[row*72 + oc + j*4];
            float4 o = *(float4*)&Ob[row*36 + oc + j*4];
            o.x = o.x*c + p.x; o.y = o.y*c + p.y;
            o.z = o.z*c + p.z; o.w = o.w*c + p.w;
            *(float4*)&Ob[row*36 + oc + j*4] = o;
        }
    }

    // epilogue: o = (O/l) * gate; split to bf16 hi/lo for the out-projection
    float inv = 1.f / l;
    size_t obase = (size_t)(q0+row)*DMOD + h*HDIM + oc;
    #pragma unroll
    for (int j = 0; j < 2; j++) {
        float4 o = *(float4*)&Ob[row*36 + oc + j*4];
        float4 g = *(const float4*)&g_gate[obase + j*4];
        float vr[4] = {o.x*inv*g.x, o.y*inv*g.y, o.z*inv*g.z, o.w*inv*g.w};
        union { bf16 h[4]; uint2 u; } H, L;
        #pragma unroll
        for (int e = 0; e < 4; e++) {
            H.h[e] = __float2bfloat16(vr[e]);
            L.h[e] = __float2bfloat16(vr[e] - __bfloat162float(H.h[e]));
        }
        *(uint2*)&g_oa_hi[obase + j*4] = H.u;
        *(uint2*)&g_oa_lo[obase + j*4] = L.u;
    }
}

extern "C" void kernel_launch(void* const* d_in, const int* in_sizes, int n_in,
                              void* d_out, int out_size)
{
    const float* s   = (const float*)d_in[0];
    const float* z   = (const float*)d_in[1];
    const float* nsw = (const float*)d_in[2];
    const float* nsb = (const float*)d_in[3];
    const float* Wq  = (const float*)d_in[4];
    const float* bq  = (const float*)d_in[5];
    const float* Wk  = (const float*)d_in[6];
    const float* Wv  = (const float*)d_in[7];
    const float* Wg  = (const float*)d_in[8];
    const float* zw  = (const float*)d_in[9];
    const float* zb  = (const float*)d_in[10];
    const float* Wz  = (const float*)d_in[11];
    const float* Wo  = (const float*)d_in[12];
    float* out = (float*)d_out;

    cudaFuncSetAttribute(tc_gemm, cudaFuncAttributeMaxDynamicSharedMemorySize, 73728);
    cudaFuncSetAttribute(flash_kernel, cudaFuncAttributeMaxDynamicSharedMemorySize, 76800);

    prep_kernel<<<1, 256>>>(Wz, zw, zb);
    ln_s_kernel<<<NSEQ, 128>>>(s, nsw, nsb);
    wtrans_kernel<<<dim3(16,16,5), dim3(32,8)>>>(Wq, Wk, Wv, Wg, Wo);
    tc_gemm<<<dim3(8,16,4), 256, 73728>>>(bq, nullptr, -1);
    zbias_kernel<<<NN/256, 256>>>(z);
    flash_kernel<<<dim3(NSEQ/64, NHEAD), 256, 76800>>>();
    tc_gemm<<<dim3(8,16,1), 256, 73728>>>(bq, out, 4);
}

// round 15
// speedup vs baseline: 1.0466x; 1.0379x over previous
#include <cuda_runtime.h>
#include <cuda_bf16.h>
#include <cuda_fp16.h>
#include <mma.h>
#include <math.h>
#include <stdint.h>

using namespace nvcuda;

#define NSEQ 1024
#define DMOD 512
#define NHEAD 16
#define HDIM 32
#define DZ 128
#define NN (NSEQ*NSEQ)
#define QSCALE 0.17677669529663687f

typedef unsigned long long u64;
typedef __nv_bfloat16 bf16;

__device__ float g_gate[NSEQ*DMOD];
__device__ __half g_scoresh[NHEAD*NN];
__device__ float g_wzp[DZ*NHEAD];
__device__ float g_alpha[NHEAD];
__device__ float g_beta[NHEAD];
__device__ bf16 g_sa_hi[NSEQ*DMOD], g_sa_lo[NSEQ*DMOD];
__device__ bf16 g_oa_hi[NSEQ*DMOD], g_oa_lo[NSEQ*DMOD];
__device__ bf16 g_wt_hi[5*DMOD*DMOD], g_wt_lo[5*DMOD*DMOD];
__device__ bf16 g_qh[NHEAD*NSEQ*HDIM], g_ql[NHEAD*NSEQ*HDIM];
__device__ bf16 g_kh[NHEAD*NSEQ*HDIM], g_kl[NHEAD*NSEQ*HDIM];
__device__ bf16 g_vh[NHEAD*NSEQ*HDIM], g_vl[NHEAD*NSEQ*HDIM];

__device__ __forceinline__ uint32_t s2u(const void* p) {
    uint32_t a;
    asm("{ .reg .u64 t; cvta.to.shared.u64 t, %1; cvt.u32.u64 %0, t; }" : "=r"(a) : "l"(p));
    return a;
}
__device__ __forceinline__ void cp16(void* smem, const void* g) {
    asm volatile("cp.async.cg.shared.global [%0], [%1], 16;"
                 :: "r"(s2u(smem)), "l"(g) : "memory");
}
__device__ __forceinline__ void cp_commit() {
    asm volatile("cp.async.commit_group;" ::: "memory");
}

__global__ void prep_kernel(const float* __restrict__ Wz,
                            const float* __restrict__ zw,
                            const float* __restrict__ zb)
{
    int t = threadIdx.x;
    for (int i = t; i < DZ*NHEAD; i += blockDim.x)
        g_wzp[i] = zw[i >> 4] * Wz[i];
    if (t < NHEAD) {
        float a = 0.f, b = 0.f;
        for (int c = 0; c < DZ; c++) {
            float wv = Wz[c*NHEAD + t];
            a += zw[c] * wv;
            b += zb[c] * wv;
        }
        g_alpha[t] = a;
        g_beta[t]  = b;
    }
}

__global__ __launch_bounds__(128) void ln_s_kernel(const float* __restrict__ s,
                                                   const float* __restrict__ w,
                                                   const float* __restrict__ b)
{
    __shared__ float sred[8];
    __shared__ float s_mu, s_rstd;
    int row = blockIdx.x, tid = threadIdx.x;
    float4 v = *(const float4*)&s[row*DMOD + tid*4];
    float sum = v.x + v.y + v.z + v.w;
    float ssq = v.x*v.x + v.y*v.y + v.z*v.z + v.w*v.w;
    #pragma unroll
    for (int o = 16; o; o >>= 1) {
        sum += __shfl_xor_sync(0xffffffffu, sum, o);
        ssq += __shfl_xor_sync(0xffffffffu, ssq, o);
    }
    int lane = tid & 31, wid = tid >> 5;
    if (lane == 0) { sred[wid] = sum; sred[4 + wid] = ssq; }
    __syncthreads();
    if (tid == 0) {
        float a = sred[0]+sred[1]+sred[2]+sred[3];
        float q = sred[4]+sred[5]+sred[6]+sred[7];
        float mu = a * (1.f/DMOD);
        float var = q * (1.f/DMOD) - mu*mu;
        s_mu = mu; s_rstd = rsqrtf(var + 1e-5f);
    }
    __syncthreads();
    float mu = s_mu, rstd = s_rstd;
    float4 wv = *(const float4*)&w[tid*4];
    float4 bv = *(const float4*)&b[tid*4];
    float o4[4];
    o4[0] = (v.x-mu)*rstd*wv.x + bv.x;
    o4[1] = (v.y-mu)*rstd*wv.y + bv.y;
    o4[2] = (v.z-mu)*rstd*wv.z + bv.z;
    o4[3] = (v.w-mu)*rstd*wv.w + bv.w;
    union { bf16 h[4]; uint2 u; } H, L;
    #pragma unroll
    for (int j = 0; j < 4; j++) {
        H.h[j] = __float2bfloat16(o4[j]);
        L.h[j] = __float2bfloat16(o4[j] - __bfloat162float(H.h[j]));
    }
    int idx = row*DMOD + tid*4;
    *(uint2*)&g_sa_hi[idx] = H.u;
    *(uint2*)&g_sa_lo[idx] = L.u;
}

__global__ void wtrans_kernel(const float* __restrict__ Wq, const float* __restrict__ Wk,
                              const float* __restrict__ Wv, const float* __restrict__ Wg,
                              const float* __restrict__ Wo)
{
    __shared__ float t[32][33];
    int g = blockIdx.z;
    const float* W = (g==0)?Wq:(g==1)?Wk:(g==2)?Wv:(g==3)?Wg:Wo;
    int tx = threadIdx.x, ty = threadIdx.y;
    int bx = blockIdx.x*32, by = blockIdx.y*32;
    #pragma unroll
    for (int i = 0; i < 4; i++)
        t[ty + 8*i][tx] = W[(size_t)(by + ty + 8*i)*DMOD + bx + tx];
    __syncthreads();
    size_t base = (size_t)g*DMOD*DMOD;
    #pragma unroll
    for (int i = 0; i < 4; i++) {
        int n = bx + ty + 8*i, k = by + tx;
        float v = t[tx][ty + 8*i];
        bf16 h = __float2bfloat16(v);
        g_wt_hi[base + (size_t)n*DMOD + k] = h;
        g_wt_lo[base + (size_t)n*DMOD + k] = __float2bfloat16(v - __bfloat162float(h));
    }
}

// WMMA bf16-split GEMM, 2-stage cp.async pipeline, 3-way split accumulators.
__global__ __launch_bounds__(256) void tc_gemm(const float* __restrict__ bq,
                                               float* __restrict__ Cout, int mode_sel)
{
    extern __shared__ __align__(16) char dynsm[];
    const int STAGE = 64*72*2;
    float* Cs = (float*)dynsm;

    int mode = (mode_sel < 0) ? (int)blockIdx.z : mode_sel;
    const bf16* Ah = (mode==4) ? g_oa_hi : g_sa_hi;
    const bf16* Al = (mode==4) ? g_oa_lo : g_sa_lo;
    size_t wb = (size_t)((mode==4)?4:mode)*DMOD*DMOD;
    const bf16* Bh = g_wt_hi + wb;
    const bf16* Bl = g_wt_lo + wb;

    int tid = threadIdx.x;
    int w = tid >> 5, wr = w >> 1, wc = w & 1;
    int m0 = blockIdx.y*64, n0 = blockIdx.x*64;
    int lrow = tid >> 2, lseg = (tid & 3) << 4;

    wmma::fragment<wmma::accumulator,16,16,16,float> accA[2], accB[2], accC[2];
    #pragma unroll
    for (int c = 0; c < 2; c++) {
        wmma::fill_fragment(accA[c], 0.f);
        wmma::fill_fragment(accB[c], 0.f);
        wmma::fill_fragment(accC[c], 0.f);
    }

    const bf16* gAh = Ah + (size_t)(m0+lrow)*DMOD + lseg;
    const bf16* gAl = Al + (size_t)(m0+lrow)*DMOD + lseg;
    const bf16* gBh = Bh + (size_t)(n0+lrow)*DMOD + lseg;
    const bf16* gBl = Bl + (size_t)(n0+lrow)*DMOD + lseg;
    int soff = (lrow*72 + lseg)*2;

    auto issue = [&](int ch, int st) {
        char* base = dynsm + st*4*STAGE;
        cp16(base + 0*STAGE + soff,      gAh + ch*64);
        cp16(base + 0*STAGE + soff + 16, gAh + ch*64 + 8);
        cp16(base + 1*STAGE + soff,      gAl + ch*64);
        cp16(base + 1*STAGE + soff + 16, gAl + ch*64 + 8);
        cp16(base + 2*STAGE + soff,      gBh + ch*64);
        cp16(base + 2*STAGE + soff + 16, gBh + ch*64 + 8);
        cp16(base + 3*STAGE + soff,      gBl + ch*64);
        cp16(base + 3*STAGE + soff + 16, gBl + ch*64 + 8);
        cp_commit();
    };

    issue(0, 0);
    for (int ch = 0; ch < 8; ch++) {
        int st = ch & 1;
        if (ch < 7) issue(ch+1, st^1);
        if (ch < 7) asm volatile("cp.async.wait_group 1;" ::: "memory");
        else        asm volatile("cp.async.wait_group 0;" ::: "memory");
        __syncthreads();
        bf16* Ah_s = (bf16*)(dynsm + st*4*STAGE + 0*STAGE);
        bf16* Al_s = (bf16*)(dynsm + st*4*STAGE + 1*STAGE);
        bf16* Bh_s = (bf16*)(dynsm + st*4*STAGE + 2*STAGE);
        bf16* Bl_s = (bf16*)(dynsm + st*4*STAGE + 3*STAGE);
        #pragma unroll
        for (int ks = 0; ks < 4; ks++) {
            wmma::fragment<wmma::matrix_a,16,16,16,bf16,wmma::row_major> fah, fal;
            wmma::load_matrix_sync(fah, Ah_s + (wr*16)*72 + ks*16, 72);
            wmma::load_matrix_sync(fal, Al_s + (wr*16)*72 + ks*16, 72);
            #pragma unroll
            for (int c = 0; c < 2; c++) {
                wmma::fragment<wmma::matrix_b,16,16,16,bf16,wmma::col_major> fbh, fbl;
                wmma::load_matrix_sync(fbh, Bh_s + (wc*32 + c*16)*72 + ks*16, 72);
                wmma::load_matrix_sync(fbl, Bl_s + (wc*32 + c*16)*72 + ks*16, 72);
                wmma::mma_sync(accA[c], fah, fbh, accA[c]);
                wmma::mma_sync(accB[c], fah, fbl, accB[c]);
                wmma::mma_sync(accC[c], fal, fbh, accC[c]);
            }
        }
        __syncthreads();
    }
    #pragma unroll
    for (int c = 0; c < 2; c++) {
        #pragma unroll
        for (int i = 0; i < accA[c].num_elements; i++)
            accA[c].x[i] += accB[c].x[i] + accC[c].x[i];
    }
    wmma::store_matrix_sync(Cs + (wr*16)*72 + wc*32,      accA[0], 72, wmma::mem_row_major);
    wmma::store_matrix_sync(Cs + (wr*16)*72 + wc*32 + 16, accA[1], 72, wmma::mem_row_major);
    __syncthreads();

    int r = lrow;
    int colg = n0 + lseg;
    if (mode <= 2) {
        bf16* dh = (mode==0) ? g_qh : (mode==1 ? g_kh : g_vh);
        bf16* dl = (mode==0) ? g_ql : (mode==1 ? g_kl : g_vl);
        size_t base = ((size_t)(colg >> 5)*NSEQ + m0 + r)*HDIM + (colg & 31);
        #pragma unroll
        for (int j = 0; j < 4; j++) {
            float4 v = *(float4*)&Cs[r*72 + lseg + j*4];
            if (mode == 0) {
                float4 bb = *(const float4*)&bq[colg + j*4];
                v.x = (v.x + bb.x)*QSCALE; v.y = (v.y + bb.y)*QSCALE;
                v.z = (v.z + bb.z)*QSCALE; v.w = (v.w + bb.w)*QSCALE;
            }
            float vr[4] = {v.x, v.y, v.z, v.w};
            union { bf16 h[4]; uint2 u; } H, L;
            #pragma unroll
            for (int e = 0; e < 4; e++) {
                H.h[e] = __float2bfloat16(vr[e]);
                L.h[e] = __float2bfloat16(vr[e] - __bfloat162float(H.h[e]));
            }
            *(uint2*)&dh[base + j*4] = H.u;
            *(uint2*)&dl[base + j*4] = L.u;
        }
    } else if (mode == 3) {
        float* dp = &g_gate[(size_t)(m0 + r)*DMOD + colg];
        #pragma unroll
        for (int j = 0; j < 4; j++) {
            float4 v = *(float4*)&Cs[r*72 + lseg + j*4];
            v.x = 1.f/(1.f + __expf(-v.x)); v.y = 1.f/(1.f + __expf(-v.y));
            v.z = 1.f/(1.f + __expf(-v.z)); v.w = 1.f/(1.f + __expf(-v.w));
            *(float4*)&dp[j*4] = v;
        }
    } else {
        float* dp = &Cout[(size_t)(m0 + r)*DMOD + colg];
        #pragma unroll
        for (int j = 0; j < 4; j++)
            *(float4*)&dp[j*4] = *(float4*)&Cs[r*72 + lseg + j*4];
    }
}

// fused LN(z)@Wz on tensor cores (unchanged).
__global__ __launch_bounds__(256) void zbias_kernel(const float* __restrict__ z)
{
    __shared__ __align__(16) bf16 wzh[DZ][16];
    __shared__ __align__(16) bf16 wzl[DZ][16];
    __shared__ __align__(16) bf16 ztile[8][2][32][40];
    int tid = threadIdx.x, lane = tid & 31, w = tid >> 5;

    for (int i = tid; i < DZ*NHEAD; i += 256) {
        float v = g_wzp[i];
        bf16 h = __float2bfloat16(v);
        wzh[i >> 4][i & 15] = h;
        wzl[i >> 4][i & 15] = __float2bfloat16(v - __bfloat162float(h));
    }
    __syncthreads();

    int row0w = blockIdx.x*256 + w*32;
    const float* zwarp = z + (size_t)row0w*DZ;
    int lr8 = lane >> 3, lc8 = (lane & 7) << 2;

    wmma::fragment<wmma::accumulator,16,16,16,float> accA[2], accB[2], accC[2];
    #pragma unroll
    for (int rt = 0; rt < 2; rt++) {
        wmma::fill_fragment(accA[rt], 0.f);
        wmma::fill_fragment(accB[rt], 0.f);
        wmma::fill_fragment(accC[rt], 0.f);
    }
    float sumj[8], ssqj[8];
    #pragma unroll
    for (int j = 0; j < 8; j++) { sumj[j] = 0.f; ssqj[j] = 0.f; }

    bf16 (*zh)[40] = ztile[w][0];
    bf16 (*zl)[40] = ztile[w][1];

    float4 cur[8];
    #pragma unroll
    for (int j = 0; j < 8; j++)
        cur[j] = *(const float4*)&zwarp[(size_t)(j*4 + lr8)*DZ + lc8];

    for (int ch = 0; ch < 4; ch++) {
        #pragma unroll
        for (int j = 0; j < 8; j++) {
            float vr[4] = {cur[j].x, cur[j].y, cur[j].z, cur[j].w};
            union { bf16 h[4]; uint2 u; } H, L;
            #pragma unroll
            for (int e = 0; e < 4; e++) {
                H.h[e] = __float2bfloat16(vr[e]);
                L.h[e] = __float2bfloat16(vr[e] - __bfloat162float(H.h[e]));
                sumj[j] += vr[e];
                ssqj[j] = fmaf(vr[e], vr[e], ssqj[j]);
            }
            *(uint2*)&zh[j*4 + lr8][lc8] = H.u;
            *(uint2*)&zl[j*4 + lr8][lc8] = L.u;
        }
        __syncwarp();
        if (ch < 3) {
            #pragma unroll
            for (int j = 0; j < 8; j++)
                cur[j] = *(const float4*)&zwarp[(size_t)(j*4 + lr8)*DZ + (ch+1)*32 + lc8];
        }
        #pragma unroll
        for (int kt = 0; kt < 2; kt++) {
            wmma::fragment<wmma::matrix_b,16,16,16,bf16,wmma::row_major> fbh, fbl;
            wmma::load_matrix_sync(fbh, &wzh[ch*32 + kt*16][0], 16);
            wmma::load_matrix_sync(fbl, &wzl[ch*32 + kt*16][0], 16);
            #pragma unroll
            for (int rt = 0; rt < 2; rt++) {
                wmma::fragment<wmma::matrix_a,16,16,16,bf16,wmma::row_major> fah, fal;
                wmma::load_matrix_sync(fah, &zh[rt*16][kt*16], 40);
                wmma::load_matrix_sync(fal, &zl[rt*16][kt*16], 40);
                wmma::mma_sync(accA[rt], fah, fbh, accA[rt]);
                wmma::mma_sync(accB[rt], fah, fbl, accB[rt]);
                wmma::mma_sync(accC[rt], fal, fbh, accC[rt]);
            }
        }
        __syncwarp();
    }

    #pragma unroll
    for (int j = 0; j < 8; j++) {
        #pragma unroll
        for (int o = 1; o < 8; o <<= 1) {
            sumj[j] += __shfl_xor_sync(0xffffffffu, sumj[j], o);
            ssqj[j] += __shfl_xor_sync(0xffffffffu, ssqj[j], o);
        }
    }
    int srcLane = (lane & 3) * 8;
    float sum_own = 0.f, ssq_own = 0.f;
    #pragma unroll
    for (int j = 0; j < 8; j++) {
        float s_ = __shfl_sync(0xffffffffu, sumj[j], srcLane);
        float q_ = __shfl_sync(0xffffffffu, ssqj[j], srcLane);
        if ((lane >> 2) == j) { sum_own = s_; ssq_own = q_; }
    }

    #pragma unroll
    for (int rt = 0; rt < 2; rt++) {
        #pragma unroll
        for (int i = 0; i < accA[rt].num_elements; i++)
            accA[rt].x[i] += accB[rt].x[i] + accC[rt].x[i];
    }
    float* Cs = (float*)ztile[w];
    wmma::store_matrix_sync(Cs,          accA[0], 20, wmma::mem_row_major);
    wmma::store_matrix_sync(Cs + 16*20,  accA[1], 20, wmma::mem_row_major);
    __syncwarp();

    float mu = sum_own * (1.f/DZ);
    float var = ssq_own * (1.f/DZ) - mu*mu;
    float rstd = rsqrtf(var + 1e-5f);
    int row = row0w + lane;
    #pragma unroll
    for (int h = 0; h < NHEAD; h++) {
        float a = Cs[lane*20 + h];
        g_scoresh[(size_t)h*NN + row] =
            __float2half(rstd*(a - mu*g_alpha[h]) + g_beta[h]);
    }
}

// Flash attention v4 (unchanged from R14).
__global__ void __launch_bounds__(256, 2) flash_kernel()
{
    extern __shared__ __align__(16) char fsm[];
    bf16* Qh = (bf16*)fsm;
    bf16* Ql = Qh + 64*40;
    bf16* Kh = Ql + 64*40;
    bf16* Kl = Kh + 64*40;
    bf16* Vh = Kl + 64*40;
    bf16* Vl = Vh + 64*40;
    float* S  = (float*)(fsm + 30720);
    bf16* Ph = (bf16*)(fsm + 49152);
    bf16* Pl = Ph + 64*72;
    float* Ob = (float*)(fsm + 67584);

    int tid = threadIdx.x, w = tid >> 5;
    int h = blockIdx.y, q0 = blockIdx.x*64;
    size_t hb = (size_t)h*NSEQ*HDIM;
    const __half* zp = g_scoresh + (size_t)h*NN;

    int row = tid >> 2;
    int seg8 = (tid & 3) << 3;
    *(uint4*)&Qh[row*40 + seg8] = *(const uint4*)&g_qh[hb + (size_t)(q0+row)*HDIM + seg8];
    *(uint4*)&Ql[row*40 + seg8] = *(const uint4*)&g_ql[hb + (size_t)(q0+row)*HDIM + seg8];
    for (int i = tid; i < 64*36; i += 256) Ob[i] = 0.f;

    float m = -1e30f, l = 0.f;
    int colb = (tid & 3) << 4;
    int oc = (tid & 3) << 3;

    for (int kb = 0; kb < NSEQ; kb += 64) {
        uint4 kh = *(const uint4*)&g_kh[hb + (size_t)(kb+row)*HDIM + seg8];
        uint4 kl = *(const uint4*)&g_kl[hb + (size_t)(kb+row)*HDIM + seg8];
        uint4 vh = *(const uint4*)&g_vh[hb + (size_t)(kb+row)*HDIM + seg8];
        uint4 vl = *(const uint4*)&g_vl[hb + (size_t)(kb+row)*HDIM + seg8];
        __syncthreads();
        *(uint4*)&Kh[row*40 + seg8] = kh;
        *(uint4*)&Kl[row*40 + seg8] = kl;
        *(uint4*)&Vh[row*40 + seg8] = vh;
        *(uint4*)&Vl[row*40 + seg8] = vl;
        __syncthreads();

        {
            int mr = w >> 1;
            wmma::fragment<wmma::accumulator,16,16,16,float> sa[2];
            wmma::fill_fragment(sa[0], 0.f);
            wmma::fill_fragment(sa[1], 0.f);
            #pragma unroll
            for (int ks = 0; ks < 2; ks++) {
                wmma::fragment<wmma::matrix_a,16,16,16,bf16,wmma::row_major> qhf, qlf;
                wmma::load_matrix_sync(qhf, Qh + (mr*16)*40 + ks*16, 40);
                wmma::load_matrix_sync(qlf, Ql + (mr*16)*40 + ks*16, 40);
                #pragma unroll
                for (int c = 0; c < 2; c++) {
                    int nc = (w & 1) + c*2;
                    wmma::fragment<wmma::matrix_b,16,16,16,bf16,wmma::col_major> kbh, kbl;
                    wmma::load_matrix_sync(kbh, Kh + (nc*16)*40 + ks*16, 40);
                    wmma::load_matrix_sync(kbl, Kl + (nc*16)*40 + ks*16, 40);
                    wmma::mma_sync(sa[c], qhf, kbh, sa[c]);
                    wmma::mma_sync(sa[c], qhf, kbl, sa[c]);
                    wmma::mma_sync(sa[c], qlf, kbh, sa[c]);
                }
            }
            wmma::store_matrix_sync(S + (mr*16)*72 + (w&1)*16,     sa[0], 72, wmma::mem_row_major);
            wmma::store_matrix_sync(S + (mr*16)*72 + ((w&1)+2)*16, sa[1], 72, wmma::mem_row_major);
        }
        __syncthreads();

        float sv[16];
        {
            union { __half hh[8]; uint4 u; } Z0, Z1;
            Z0.u = *(const uint4*)&zp[(size_t)(q0+row)*NSEQ + kb + colb];
            Z1.u = *(const uint4*)&zp[(size_t)(q0+row)*NSEQ + kb + colb + 8];
            #pragma unroll
            for (int j = 0; j < 8; j++) {
                sv[j]   = S[row*72 + colb + j]     + __half2float(Z0.hh[j]);
                sv[8+j] = S[row*72 + colb + 8 + j] + __half2float(Z1.hh[j]);
            }
        }
        float mx = sv[0];
        #pragma unroll
        for (int j = 1; j < 16; j++) mx = fmaxf(mx, sv[j]);
        mx = fmaxf(mx, __shfl_xor_sync(0xffffffffu, mx, 1));
        mx = fmaxf(mx, __shfl_xor_sync(0xffffffffu, mx, 2));
        float mnew = fmaxf(m, mx);
        float c = __expf(m - mnew);
        float rs = 0.f;
        union { bf16 h[8]; uint4 u; } PH[2], PL[2];
        #pragma unroll
        for (int j = 0; j < 16; j++) {
            float e = __expf(sv[j] - mnew);
            rs += e;
            bf16 eh = __float2bfloat16(e);
            PH[j>>3].h[j&7] = eh;
            PL[j>>3].h[j&7] = __float2bfloat16(e - __bfloat162float(eh));
        }
        rs += __shfl_xor_sync(0xffffffffu, rs, 1);
        rs += __shfl_xor_sync(0xffffffffu, rs, 2);
        l = l*c + rs;
        m = mnew;
        *(uint4*)&Ph[row*72 + colb]     = PH[0].u;
        *(uint4*)&Ph[row*72 + colb + 8] = PH[1].u;
        *(uint4*)&Pl[row*72 + colb]     = PL[0].u;
        *(uint4*)&Pl[row*72 + colb + 8] = PL[1].u;
        __syncthreads();

        {
            int mr = w >> 1, nc = w & 1;
            wmma::fragment<wmma::accumulator,16,16,16,float> oa;
            wmma::fill_fragment(oa, 0.f);
            #pragma unroll
            for (int ks = 0; ks < 4; ks++) {
                wmma::fragment<wmma::matrix_a,16,16,16,bf16,wmma::row_major> phf, plf;
                wmma::load_matrix_sync(phf, Ph + (mr*16)*72 + ks*16, 72);
                wmma::load_matrix_sync(plf, Pl + (mr*16)*72 + ks*16, 72);
                wmma::fragment<wmma::matrix_b,16,16,16,bf16,wmma::row_major> vbh, vbl;
                wmma::load_matrix_sync(vbh, Vh + (ks*16)*40 + nc*16, 40);
                wmma::load_matrix_sync(vbl, Vl + (ks*16)*40 + nc*16, 40);
                wmma::mma_sync(oa, phf, vbh, oa);
                wmma::mma_sync(oa, phf, vbl, oa);
                wmma::mma_sync(oa, plf, vbh, oa);
            }
            wmma::store_matrix_sync(S + (mr*16)*72 + nc*16, oa, 72, wmma::mem_row_major);
        }
        __syncthreads();

        #pragma unroll
        for (int j = 0; j < 2; j++) {
            float4 p = *(float4*)&S[row*72 + oc + j*4];
            float4 o = *(float4*)&Ob[row*36 + oc + j*4];
            o.x = o.x*c + p.x; o.y = o.y*c + p.y;
            o.z = o.z*c + p.z; o.w = o.w*c + p.w;
            *(float4*)&Ob[row*36 + oc + j*4] = o;
        }
    }

    float inv = 1.f / l;
    size_t obase = (size_t)(q0+row)*DMOD + h*HDIM + oc;
    #pragma unroll
    for (int j = 0; j < 2; j++) {
        float4 o = *(float4*)&Ob[row*36 + oc + j*4];
        float4 g = *(const float4*)&g_gate[obase + j*4];
        float vr[4] = {o.x*inv*g.x, o.y*inv*g.y, o.z*inv*g.z, o.w*inv*g.w};
        union { bf16 h[4]; uint2 u; } H, L;
        #pragma unroll
        for (int e = 0; e < 4; e++) {
            H.h[e] = __float2bfloat16(vr[e]);
            L.h[e] = __float2bfloat16(vr[e] - __bfloat162float(H.h[e]));
        }
        *(uint2*)&g_oa_hi[obase + j*4] = H.u;
        *(uint2*)&g_oa_lo[obase + j*4] = L.u;
    }
}

extern "C" void kernel_launch(void* const* d_in, const int* in_sizes, int n_in,
                              void* d_out, int out_size)
{
    const float* s   = (const float*)d_in[0];
    const float* z   = (const float*)d_in[1];
    const float* nsw = (const float*)d_in[2];
    const float* nsb = (const float*)d_in[3];
    const float* Wq  = (const float*)d_in[4];
    const float* bq  = (const float*)d_in[5];
    const float* Wk  = (const float*)d_in[6];
    const float* Wv  = (const float*)d_in[7];
    const float* Wg  = (const float*)d_in[8];
    const float* zw  = (const float*)d_in[9];
    const float* zb  = (const float*)d_in[10];
    const float* Wz  = (const float*)d_in[11];
    const float* Wo  = (const float*)d_in[12];
    float* out = (float*)d_out;

    // Lazily create side stream + events once (first call is uncaptured; during
    // graph capture only launches/event ops run, which are capture-legal).
    static cudaStream_t s2 = nullptr;
    static cudaEvent_t evFork = nullptr, evJoin = nullptr;
    if (!s2) {
        cudaStreamCreateWithFlags(&s2, cudaStreamNonBlocking);
        cudaEventCreateWithFlags(&evFork, cudaEventDisableTiming);
        cudaEventCreateWithFlags(&evJoin, cudaEventDisableTiming);
    }

    cudaFuncSetAttribute(tc_gemm, cudaFuncAttributeMaxDynamicSharedMemorySize, 73728);
    cudaFuncSetAttribute(flash_kernel, cudaFuncAttributeMaxDynamicSharedMemorySize, 76800);

    // main stream: prep, then fork zbias onto side stream
    prep_kernel<<<1, 256>>>(Wz, zw, zb);
    cudaEventRecord(evFork, 0);
    cudaStreamWaitEvent(s2, evFork, 0);
    zbias_kernel<<<NN/256, 256, 0, s2>>>(z);

    // main stream: QKVG path (overlaps with zbias)
    ln_s_kernel<<<NSEQ, 128>>>(s, nsw, nsb);
    wtrans_kernel<<<dim3(16,16,5), dim3(32,8)>>>(Wq, Wk, Wv, Wg, Wo);
    tc_gemm<<<dim3(8,16,4), 256, 73728>>>(bq, nullptr, -1);

    // join: flash needs both zbias (side) and QKVG (main)
    cudaEventRecord(evJoin, s2);
    cudaStreamWaitEvent(0, evJoin, 0);
    flash_kernel<<<dim3(NSEQ/64, NHEAD), 256, 76800>>>();
    tc_gemm<<<dim3(8,16,1), 256, 73728>>>(bq, out, 4);
}

// round 16
// speedup vs baseline: 1.0489x; 1.0021x over previous
#include <cuda_runtime.h>
#include <cuda_bf16.h>
#include <cuda_fp16.h>
#include <mma.h>
#include <math.h>
#include <stdint.h>

using namespace nvcuda;

#define NSEQ 1024
#define DMOD 512
#define NHEAD 16
#define HDIM 32
#define DZ 128
#define NN (NSEQ*NSEQ)
#define QSCALE 0.17677669529663687f

typedef unsigned long long u64;
typedef __nv_bfloat16 bf16;

__device__ float g_gate[NSEQ*DMOD];
__device__ __half g_scoresh[NHEAD*NN];
__device__ float g_wzp[DZ*NHEAD];
__device__ float g_alpha[NHEAD];
__device__ float g_beta[NHEAD];
__device__ bf16 g_sa_hi[NSEQ*DMOD], g_sa_lo[NSEQ*DMOD];
__device__ bf16 g_oa_hi[NSEQ*DMOD], g_oa_lo[NSEQ*DMOD];
__device__ bf16 g_wt_hi[5*DMOD*DMOD], g_wt_lo[5*DMOD*DMOD];
__device__ bf16 g_qh[NHEAD*NSEQ*HDIM], g_ql[NHEAD*NSEQ*HDIM];
__device__ bf16 g_kh[NHEAD*NSEQ*HDIM], g_kl[NHEAD*NSEQ*HDIM];
__device__ bf16 g_vh[NHEAD*NSEQ*HDIM], g_vl[NHEAD*NSEQ*HDIM];

__device__ __forceinline__ uint32_t s2u(const void* p) {
    uint32_t a;
    asm("{ .reg .u64 t; cvta.to.shared.u64 t, %1; cvt.u32.u64 %0, t; }" : "=r"(a) : "l"(p));
    return a;
}
__device__ __forceinline__ void cp16(void* smem, const void* g) {
    asm volatile("cp.async.cg.shared.global [%0], [%1], 16;"
                 :: "r"(s2u(smem)), "l"(g) : "memory");
}
__device__ __forceinline__ void cp_commit() {
    asm volatile("cp.async.commit_group;" ::: "memory");
}

__global__ void prep_kernel(const float* __restrict__ Wz,
                            const float* __restrict__ zw,
                            const float* __restrict__ zb)
{
    int t = threadIdx.x;
    for (int i = t; i < DZ*NHEAD; i += blockDim.x)
        g_wzp[i] = zw[i >> 4] * Wz[i];
    if (t < NHEAD) {
        float a = 0.f, b = 0.f;
        for (int c = 0; c < DZ; c++) {
            float wv = Wz[c*NHEAD + t];
            a += zw[c] * wv;
            b += zb[c] * wv;
        }
        g_alpha[t] = a;
        g_beta[t]  = b;
    }
}

__global__ __launch_bounds__(128) void ln_s_kernel(const float* __restrict__ s,
                                                   const float* __restrict__ w,
                                                   const float* __restrict__ b)
{
    __shared__ float sred[8];
    __shared__ float s_mu, s_rstd;
    int row = blockIdx.x, tid = threadIdx.x;
    float4 v = *(const float4*)&s[row*DMOD + tid*4];
    float sum = v.x + v.y + v.z + v.w;
    float ssq = v.x*v.x + v.y*v.y + v.z*v.z + v.w*v.w;
    #pragma unroll
    for (int o = 16; o; o >>= 1) {
        sum += __shfl_xor_sync(0xffffffffu, sum, o);
        ssq += __shfl_xor_sync(0xffffffffu, ssq, o);
    }
    int lane = tid & 31, wid = tid >> 5;
    if (lane == 0) { sred[wid] = sum; sred[4 + wid] = ssq; }
    __syncthreads();
    if (tid == 0) {
        float a = sred[0]+sred[1]+sred[2]+sred[3];
        float q = sred[4]+sred[5]+sred[6]+sred[7];
        float mu = a * (1.f/DMOD);
        float var = q * (1.f/DMOD) - mu*mu;
        s_mu = mu; s_rstd = rsqrtf(var + 1e-5f);
    }
    __syncthreads();
    float mu = s_mu, rstd = s_rstd;
    float4 wv = *(const float4*)&w[tid*4];
    float4 bv = *(const float4*)&b[tid*4];
    float o4[4];
    o4[0] = (v.x-mu)*rstd*wv.x + bv.x;
    o4[1] = (v.y-mu)*rstd*wv.y + bv.y;
    o4[2] = (v.z-mu)*rstd*wv.z + bv.z;
    o4[3] = (v.w-mu)*rstd*wv.w + bv.w;
    union { bf16 h[4]; uint2 u; } H, L;
    #pragma unroll
    for (int j = 0; j < 4; j++) {
        H.h[j] = __float2bfloat16(o4[j]);
        L.h[j] = __float2bfloat16(o4[j] - __bfloat162float(H.h[j]));
    }
    int idx = row*DMOD + tid*4;
    *(uint2*)&g_sa_hi[idx] = H.u;
    *(uint2*)&g_sa_lo[idx] = L.u;
}

__global__ void wtrans_kernel(const float* __restrict__ Wq, const float* __restrict__ Wk,
                              const float* __restrict__ Wv, const float* __restrict__ Wg,
                              const float* __restrict__ Wo)
{
    __shared__ float t[32][33];
    int g = blockIdx.z;
    const float* W = (g==0)?Wq:(g==1)?Wk:(g==2)?Wv:(g==3)?Wg:Wo;
    int tx = threadIdx.x, ty = threadIdx.y;
    int bx = blockIdx.x*32, by = blockIdx.y*32;
    #pragma unroll
    for (int i = 0; i < 4; i++)
        t[ty + 8*i][tx] = W[(size_t)(by + ty + 8*i)*DMOD + bx + tx];
    __syncthreads();
    size_t base = (size_t)g*DMOD*DMOD;
    #pragma unroll
    for (int i = 0; i < 4; i++) {
        int n = bx + ty + 8*i, k = by + tx;
        float v = t[tx][ty + 8*i];
        bf16 h = __float2bfloat16(v);
        g_wt_hi[base + (size_t)n*DMOD + k] = h;
        g_wt_lo[base + (size_t)n*DMOD + k] = __float2bfloat16(v - __bfloat162float(h));
    }
}

// WMMA bf16-split GEMM, 2-stage cp.async pipeline, 3-way split accumulators.
__global__ __launch_bounds__(256) void tc_gemm(const float* __restrict__ bq,
                                               float* __restrict__ Cout, int mode_sel)
{
    extern __shared__ __align__(16) char dynsm[];
    const int STAGE = 64*72*2;
    float* Cs = (float*)dynsm;

    int mode = (mode_sel < 0) ? (int)blockIdx.z : mode_sel;
    const bf16* Ah = (mode==4) ? g_oa_hi : g_sa_hi;
    const bf16* Al = (mode==4) ? g_oa_lo : g_sa_lo;
    size_t wb = (size_t)((mode==4)?4:mode)*DMOD*DMOD;
    const bf16* Bh = g_wt_hi + wb;
    const bf16* Bl = g_wt_lo + wb;

    int tid = threadIdx.x;
    int w = tid >> 5, wr = w >> 1, wc = w & 1;
    int m0 = blockIdx.y*64, n0 = blockIdx.x*64;
    int lrow = tid >> 2, lseg = (tid & 3) << 4;

    wmma::fragment<wmma::accumulator,16,16,16,float> accA[2], accB[2], accC[2];
    #pragma unroll
    for (int c = 0; c < 2; c++) {
        wmma::fill_fragment(accA[c], 0.f);
        wmma::fill_fragment(accB[c], 0.f);
        wmma::fill_fragment(accC[c], 0.f);
    }

    const bf16* gAh = Ah + (size_t)(m0+lrow)*DMOD + lseg;
    const bf16* gAl = Al + (size_t)(m0+lrow)*DMOD + lseg;
    const bf16* gBh = Bh + (size_t)(n0+lrow)*DMOD + lseg;
    const bf16* gBl = Bl + (size_t)(n0+lrow)*DMOD + lseg;
    int soff = (lrow*72 + lseg)*2;

    auto issue = [&](int ch, int st) {
        char* base = dynsm + st*4*STAGE;
        cp16(base + 0*STAGE + soff,      gAh + ch*64);
        cp16(base + 0*STAGE + soff + 16, gAh + ch*64 + 8);
        cp16(base + 1*STAGE + soff,      gAl + ch*64);
        cp16(base + 1*STAGE + soff + 16, gAl + ch*64 + 8);
        cp16(base + 2*STAGE + soff,      gBh + ch*64);
        cp16(base + 2*STAGE + soff + 16, gBh + ch*64 + 8);
        cp16(base + 3*STAGE + soff,      gBl + ch*64);
        cp16(base + 3*STAGE + soff + 16, gBl + ch*64 + 8);
        cp_commit();
    };

    issue(0, 0);
    for (int ch = 0; ch < 8; ch++) {
        int st = ch & 1;
        if (ch < 7) issue(ch+1, st^1);
        if (ch < 7) asm volatile("cp.async.wait_group 1;" ::: "memory");
        else        asm volatile("cp.async.wait_group 0;" ::: "memory");
        __syncthreads();
        bf16* Ah_s = (bf16*)(dynsm + st*4*STAGE + 0*STAGE);
        bf16* Al_s = (bf16*)(dynsm + st*4*STAGE + 1*STAGE);
        bf16* Bh_s = (bf16*)(dynsm + st*4*STAGE + 2*STAGE);
        bf16* Bl_s = (bf16*)(dynsm + st*4*STAGE + 3*STAGE);
        #pragma unroll
        for (int ks = 0; ks < 4; ks++) {
            wmma::fragment<wmma::matrix_a,16,16,16,bf16,wmma::row_major> fah, fal;
            wmma::load_matrix_sync(fah, Ah_s + (wr*16)*72 + ks*16, 72);
            wmma::load_matrix_sync(fal, Al_s + (wr*16)*72 + ks*16, 72);
            #pragma unroll
            for (int c = 0; c < 2; c++) {
                wmma::fragment<wmma::matrix_b,16,16,16,bf16,wmma::col_major> fbh, fbl;
                wmma::load_matrix_sync(fbh, Bh_s + (wc*32 + c*16)*72 + ks*16, 72);
                wmma::load_matrix_sync(fbl, Bl_s + (wc*32 + c*16)*72 + ks*16, 72);
                wmma::mma_sync(accA[c], fah, fbh, accA[c]);
                wmma::mma_sync(accB[c], fah, fbl, accB[c]);
                wmma::mma_sync(accC[c], fal, fbh, accC[c]);
            }
        }
        __syncthreads();
    }
    #pragma unroll
    for (int c = 0; c < 2; c++) {
        #pragma unroll
        for (int i = 0; i < accA[c].num_elements; i++)
            accA[c].x[i] += accB[c].x[i] + accC[c].x[i];
    }
    wmma::store_matrix_sync(Cs + (wr*16)*72 + wc*32,      accA[0], 72, wmma::mem_row_major);
    wmma::store_matrix_sync(Cs + (wr*16)*72 + wc*32 + 16, accA[1], 72, wmma::mem_row_major);
    __syncthreads();

    int r = lrow;
    int colg = n0 + lseg;
    if (mode <= 2) {
        bf16* dh = (mode==0) ? g_qh : (mode==1 ? g_kh : g_vh);
        bf16* dl = (mode==0) ? g_ql : (mode==1 ? g_kl : g_vl);
        size_t base = ((size_t)(colg >> 5)*NSEQ + m0 + r)*HDIM + (colg & 31);
        #pragma unroll
        for (int j = 0; j < 4; j++) {
            float4 v = *(float4*)&Cs[r*72 + lseg + j*4];
            if (mode == 0) {
                float4 bb = *(const float4*)&bq[colg + j*4];
                v.x = (v.x + bb.x)*QSCALE; v.y = (v.y + bb.y)*QSCALE;
                v.z = (v.z + bb.z)*QSCALE; v.w = (v.w + bb.w)*QSCALE;
            }
            float vr[4] = {v.x, v.y, v.z, v.w};
            union { bf16 h[4]; uint2 u; } H, L;
            #pragma unroll
            for (int e = 0; e < 4; e++) {
                H.h[e] = __float2bfloat16(vr[e]);
                L.h[e] = __float2bfloat16(vr[e] - __bfloat162float(H.h[e]));
            }
            *(uint2*)&dh[base + j*4] = H.u;
            *(uint2*)&dl[base + j*4] = L.u;
        }
    } else if (mode == 3) {
        float* dp = &g_gate[(size_t)(m0 + r)*DMOD + colg];
        #pragma unroll
        for (int j = 0; j < 4; j++) {
            float4 v = *(float4*)&Cs[r*72 + lseg + j*4];
            v.x = 1.f/(1.f + __expf(-v.x)); v.y = 1.f/(1.f + __expf(-v.y));
            v.z = 1.f/(1.f + __expf(-v.z)); v.w = 1.f/(1.f + __expf(-v.w));
            *(float4*)&dp[j*4] = v;
        }
    } else {
        float* dp = &Cout[(size_t)(m0 + r)*DMOD + colg];
        #pragma unroll
        for (int j = 0; j < 4; j++)
            *(float4*)&dp[j*4] = *(float4*)&Cs[r*72 + lseg + j*4];
    }
}

// fused LN(z)@Wz on tensor cores (unchanged).
__global__ __launch_bounds__(256) void zbias_kernel(const float* __restrict__ z)
{
    __shared__ __align__(16) bf16 wzh[DZ][16];
    __shared__ __align__(16) bf16 wzl[DZ][16];
    __shared__ __align__(16) bf16 ztile[8][2][32][40];
    int tid = threadIdx.x, lane = tid & 31, w = tid >> 5;

    for (int i = tid; i < DZ*NHEAD; i += 256) {
        float v = g_wzp[i];
        bf16 h = __float2bfloat16(v);
        wzh[i >> 4][i & 15] = h;
        wzl[i >> 4][i & 15] = __float2bfloat16(v - __bfloat162float(h));
    }
    __syncthreads();

    int row0w = blockIdx.x*256 + w*32;
    const float* zwarp = z + (size_t)row0w*DZ;
    int lr8 = lane >> 3, lc8 = (lane & 7) << 2;

    wmma::fragment<wmma::accumulator,16,16,16,float> accA[2], accB[2], accC[2];
    #pragma unroll
    for (int rt = 0; rt < 2; rt++) {
        wmma::fill_fragment(accA[rt], 0.f);
        wmma::fill_fragment(accB[rt], 0.f);
        wmma::fill_fragment(accC[rt], 0.f);
    }
    float sumj[8], ssqj[8];
    #pragma unroll
    for (int j = 0; j < 8; j++) { sumj[j] = 0.f; ssqj[j] = 0.f; }

    bf16 (*zh)[40] = ztile[w][0];
    bf16 (*zl)[40] = ztile[w][1];

    float4 cur[8];
    #pragma unroll
    for (int j = 0; j < 8; j++)
        cur[j] = *(const float4*)&zwarp[(size_t)(j*4 + lr8)*DZ + lc8];

    for (int ch = 0; ch < 4; ch++) {
        #pragma unroll
        for (int j = 0; j < 8; j++) {
            float vr[4] = {cur[j].x, cur[j].y, cur[j].z, cur[j].w};
            union { bf16 h[4]; uint2 u; } H, L;
            #pragma unroll
            for (int e = 0; e < 4; e++) {
                H.h[e] = __float2bfloat16(vr[e]);
                L.h[e] = __float2bfloat16(vr[e] - __bfloat162float(H.h[e]));
                sumj[j] += vr[e];
                ssqj[j] = fmaf(vr[e], vr[e], ssqj[j]);
            }
            *(uint2*)&zh[j*4 + lr8][lc8] = H.u;
            *(uint2*)&zl[j*4 + lr8][lc8] = L.u;
        }
        __syncwarp();
        if (ch < 3) {
            #pragma unroll
            for (int j = 0; j < 8; j++)
                cur[j] = *(const float4*)&zwarp[(size_t)(j*4 + lr8)*DZ + (ch+1)*32 + lc8];
        }
        #pragma unroll
        for (int kt = 0; kt < 2; kt++) {
            wmma::fragment<wmma::matrix_b,16,16,16,bf16,wmma::row_major> fbh, fbl;
            wmma::load_matrix_sync(fbh, &wzh[ch*32 + kt*16][0], 16);
            wmma::load_matrix_sync(fbl, &wzl[ch*32 + kt*16][0], 16);
            #pragma unroll
            for (int rt = 0; rt < 2; rt++) {
                wmma::fragment<wmma::matrix_a,16,16,16,bf16,wmma::row_major> fah, fal;
                wmma::load_matrix_sync(fah, &zh[rt*16][kt*16], 40);
                wmma::load_matrix_sync(fal, &zl[rt*16][kt*16], 40);
                wmma::mma_sync(accA[rt], fah, fbh, accA[rt]);
                wmma::mma_sync(accB[rt], fah, fbl, accB[rt]);
                wmma::mma_sync(accC[rt], fal, fbh, accC[rt]);
            }
        }
        __syncwarp();
    }

    #pragma unroll
    for (int j = 0; j < 8; j++) {
        #pragma unroll
        for (int o = 1; o < 8; o <<= 1) {
            sumj[j] += __shfl_xor_sync(0xffffffffu, sumj[j], o);
            ssqj[j] += __shfl_xor_sync(0xffffffffu, ssqj[j], o);
        }
    }
    int srcLane = (lane & 3) * 8;
    float sum_own = 0.f, ssq_own = 0.f;
    #pragma unroll
    for (int j = 0; j < 8; j++) {
        float s_ = __shfl_sync(0xffffffffu, sumj[j], srcLane);
        float q_ = __shfl_sync(0xffffffffu, ssqj[j], srcLane);
        if ((lane >> 2) == j) { sum_own = s_; ssq_own = q_; }
    }

    #pragma unroll
    for (int rt = 0; rt < 2; rt++) {
        #pragma unroll
        for (int i = 0; i < accA[rt].num_elements; i++)
            accA[rt].x[i] += accB[rt].x[i] + accC[rt].x[i];
    }
    float* Cs = (float*)ztile[w];
    wmma::store_matrix_sync(Cs,          accA[0], 20, wmma::mem_row_major);
    wmma::store_matrix_sync(Cs + 16*20,  accA[1], 20, wmma::mem_row_major);
    __syncwarp();

    float mu = sum_own * (1.f/DZ);
    float var = ssq_own * (1.f/DZ) - mu*mu;
    float rstd = rsqrtf(var + 1e-5f);
    int row = row0w + lane;
    #pragma unroll
    for (int h = 0; h < NHEAD; h++) {
        float a = Cs[lane*20 + h];
        g_scoresh[(size_t)h*NN + row] =
            __float2half(rstd*(a - mu*g_alpha[h]) + g_beta[h]);
    }
}

// Flash attention v5: 2-stage cp.async K/V pipeline hides global-load latency.
// smem layout (97280 B, 2 CTA/SM):
//   Qh 0, Ql 5120; KV stage s at 10240+s*20480 {Kh,+5120 Kl,+10240 Vh,+15360 Vl};
//   S fp32 at 51200 [64][72]; Ph 69632, Pl 78848 [64][72] bf16; Ob 88064 [64][36].
__global__ void __launch_bounds__(256, 2) flash_kernel()
{
    extern __shared__ __align__(16) char fsm[];
    bf16* Qh = (bf16*)fsm;
    bf16* Ql = (bf16*)(fsm + 5120);
    float* S  = (float*)(fsm + 51200);
    bf16* Ph = (bf16*)(fsm + 69632);
    bf16* Pl = (bf16*)(fsm + 78848);
    float* Ob = (float*)(fsm + 88064);

    int tid = threadIdx.x, w = tid >> 5;
    int h = blockIdx.y, q0 = blockIdx.x*64;
    size_t hb = (size_t)h*NSEQ*HDIM;
    const __half* zp = g_scoresh + (size_t)h*NN;

    int row = tid >> 2;
    int seg8 = (tid & 3) << 3;
    int koff = (row*40 + seg8)*2;     // byte offset within a K/V array

    *(uint4*)&Qh[row*40 + seg8] = *(const uint4*)&g_qh[hb + (size_t)(q0+row)*HDIM + seg8];
    *(uint4*)&Ql[row*40 + seg8] = *(const uint4*)&g_ql[hb + (size_t)(q0+row)*HDIM + seg8];
    for (int i = tid; i < 64*36; i += 256) Ob[i] = 0.f;

    auto issue = [&](int kbi, int st) {
        char* base = fsm + 10240 + st*20480;
        size_t g = hb + (size_t)(kbi*64 + row)*HDIM + seg8;
        cp16(base + koff,         &g_kh[g]);
        cp16(base + 5120 + koff,  &g_kl[g]);
        cp16(base + 10240 + koff, &g_vh[g]);
        cp16(base + 15360 + koff, &g_vl[g]);
        cp_commit();
    };

    float m = -1e30f, l = 0.f;
    int colb = (tid & 3) << 4;
    int oc = (tid & 3) << 3;

    issue(0, 0);
    for (int kbi = 0; kbi < 16; kbi++) {
        int st = kbi & 1;
        int kb = kbi*64;
        if (kbi < 15) issue(kbi+1, st^1);
        if (kbi < 15) asm volatile("cp.async.wait_group 1;" ::: "memory");
        else          asm volatile("cp.async.wait_group 0;" ::: "memory");
        __syncthreads();
        bf16* Kh = (bf16*)(fsm + 10240 + st*20480);
        bf16* Kl = (bf16*)(fsm + 10240 + st*20480 + 5120);
        bf16* Vh = (bf16*)(fsm + 10240 + st*20480 + 10240);
        bf16* Vl = (bf16*)(fsm + 10240 + st*20480 + 15360);

        {
            int mr = w >> 1;
            wmma::fragment<wmma::accumulator,16,16,16,float> sa[2];
            wmma::fill_fragment(sa[0], 0.f);
            wmma::fill_fragment(sa[1], 0.f);
            #pragma unroll
            for (int ks = 0; ks < 2; ks++) {
                wmma::fragment<wmma::matrix_a,16,16,16,bf16,wmma::row_major> qhf, qlf;
                wmma::load_matrix_sync(qhf, Qh + (mr*16)*40 + ks*16, 40);
                wmma::load_matrix_sync(qlf, Ql + (mr*16)*40 + ks*16, 40);
                #pragma unroll
                for (int c = 0; c < 2; c++) {
                    int nc = (w & 1) + c*2;
                    wmma::fragment<wmma::matrix_b,16,16,16,bf16,wmma::col_major> kbh, kbl;
                    wmma::load_matrix_sync(kbh, Kh + (nc*16)*40 + ks*16, 40);
                    wmma::load_matrix_sync(kbl, Kl + (nc*16)*40 + ks*16, 40);
                    wmma::mma_sync(sa[c], qhf, kbh, sa[c]);
                    wmma::mma_sync(sa[c], qhf, kbl, sa[c]);
                    wmma::mma_sync(sa[c], qlf, kbh, sa[c]);
                }
            }
            wmma::store_matrix_sync(S + (mr*16)*72 + (w&1)*16,     sa[0], 72, wmma::mem_row_major);
            wmma::store_matrix_sync(S + (mr*16)*72 + ((w&1)+2)*16, sa[1], 72, wmma::mem_row_major);
        }
        __syncthreads();

        float sv[16];
        {
            union { __half hh[8]; uint4 u; } Z0, Z1;
            Z0.u = *(const uint4*)&zp[(size_t)(q0+row)*NSEQ + kb + colb];
            Z1.u = *(const uint4*)&zp[(size_t)(q0+row)*NSEQ + kb + colb + 8];
            #pragma unroll
            for (int j = 0; j < 8; j++) {
                sv[j]   = S[row*72 + colb + j]     + __half2float(Z0.hh[j]);
                sv[8+j] = S[row*72 + colb + 8 + j] + __half2float(Z1.hh[j]);
            }
        }
        float mx = sv[0];
        #pragma unroll
        for (int j = 1; j < 16; j++) mx = fmaxf(mx, sv[j]);
        mx = fmaxf(mx, __shfl_xor_sync(0xffffffffu, mx, 1));
        mx = fmaxf(mx, __shfl_xor_sync(0xffffffffu, mx, 2));
        float mnew = fmaxf(m, mx);
        float c = __expf(m - mnew);
        float rs = 0.f;
        union { bf16 h[8]; uint4 u; } PH[2], PL[2];
        #pragma unroll
        for (int j = 0; j < 16; j++) {
            float e = __expf(sv[j] - mnew);
            rs += e;
            bf16 eh = __float2bfloat16(e);
            PH[j>>3].h[j&7] = eh;
            PL[j>>3].h[j&7] = __float2bfloat16(e - __bfloat162float(eh));
        }
        rs += __shfl_xor_sync(0xffffffffu, rs, 1);
        rs += __shfl_xor_sync(0xffffffffu, rs, 2);
        l = l*c + rs;
        m = mnew;
        *(uint4*)&Ph[row*72 + colb]     = PH[0].u;
        *(uint4*)&Ph[row*72 + colb + 8] = PH[1].u;
        *(uint4*)&Pl[row*72 + colb]     = PL[0].u;
        *(uint4*)&Pl[row*72 + colb + 8] = PL[1].u;
        __syncthreads();

        {
            int mr = w >> 1, nc = w & 1;
            wmma::fragment<wmma::accumulator,16,16,16,float> oa;
            wmma::fill_fragment(oa, 0.f);
            #pragma unroll
            for (int ks = 0; ks < 4; ks++) {
                wmma::fragment<wmma::matrix_a,16,16,16,bf16,wmma::row_major> phf, plf;
                wmma::load_matrix_sync(phf, Ph + (mr*16)*72 + ks*16, 72);
                wmma::load_matrix_sync(plf, Pl + (mr*16)*72 + ks*16, 72);
                wmma::fragment<wmma::matrix_b,16,16,16,bf16,wmma::row_major> vbh, vbl;
                wmma::load_matrix_sync(vbh, Vh + (ks*16)*40 + nc*16, 40);
                wmma::load_matrix_sync(vbl, Vl + (ks*16)*40 + nc*16, 40);
                wmma::mma_sync(oa, phf, vbh, oa);
                wmma::mma_sync(oa, phf, vbl, oa);
                wmma::mma_sync(oa, plf, vbh, oa);
            }
            wmma::store_matrix_sync(S + (mr*16)*72 + nc*16, oa, 72, wmma::mem_row_major);
        }
        __syncthreads();

        #pragma unroll
        for (int j = 0; j < 2; j++) {
            float4 p = *(float4*)&S[row*72 + oc + j*4];
            float4 o = *(float4*)&Ob[row*36 + oc + j*4];
            o.x = o.x*c + p.x; o.y = o.y*c + p.y;
            o.z = o.z*c + p.z; o.w = o.w*c + p.w;
            *(float4*)&Ob[row*36 + oc + j*4] = o;
        }
    }

    float inv = 1.f / l;
    size_t obase = (size_t)(q0+row)*DMOD + h*HDIM + oc;
    #pragma unroll
    for (int j = 0; j < 2; j++) {
        float4 o = *(float4*)&Ob[row*36 + oc + j*4];
        float4 g = *(const float4*)&g_gate[obase + j*4];
        float vr[4] = {o.x*inv*g.x, o.y*inv*g.y, o.z*inv*g.z, o.w*inv*g.w};
        union { bf16 h[4]; uint2 u; } H, L;
        #pragma unroll
        for (int e = 0; e < 4; e++) {
            H.h[e] = __float2bfloat16(vr[e]);
            L.h[e] = __float2bfloat16(vr[e] - __bfloat162float(H.h[e]));
        }
        *(uint2*)&g_oa_hi[obase + j*4] = H.u;
        *(uint2*)&g_oa_lo[obase + j*4] = L.u;
    }
}

extern "C" void kernel_launch(void* const* d_in, const int* in_sizes, int n_in,
                              void* d_out, int out_size)
{
    const float* s   = (const float*)d_in[0];
    const float* z   = (const float*)d_in[1];
    const float* nsw = (const float*)d_in[2];
    const float* nsb = (const float*)d_in[3];
    const float* Wq  = (const float*)d_in[4];
    const float* bq  = (const float*)d_in[5];
    const float* Wk  = (const float*)d_in[6];
    const float* Wv  = (const float*)d_in[7];
    const float* Wg  = (const float*)d_in[8];
    const float* zw  = (const float*)d_in[9];
    const float* zb  = (const float*)d_in[10];
    const float* Wz  = (const float*)d_in[11];
    const float* Wo  = (const float*)d_in[12];
    float* out = (float*)d_out;

    static cudaStream_t s2 = nullptr;
    static cudaEvent_t evFork = nullptr, evJoin = nullptr;
    if (!s2) {
        cudaStreamCreateWithFlags(&s2, cudaStreamNonBlocking);
        cudaEventCreateWithFlags(&evFork, cudaEventDisableTiming);
        cudaEventCreateWithFlags(&evJoin, cudaEventDisableTiming);
    }

    cudaFuncSetAttribute(tc_gemm, cudaFuncAttributeMaxDynamicSharedMemorySize, 73728);
    cudaFuncSetAttribute(flash_kernel, cudaFuncAttributeMaxDynamicSharedMemorySize, 97280);

    prep_kernel<<<1, 256>>>(Wz, zw, zb);
    cudaEventRecord(evFork, 0);
    cudaStreamWaitEvent(s2, evFork, 0);
    zbias_kernel<<<NN/256, 256, 0, s2>>>(z);

    ln_s_kernel<<<NSEQ, 128>>>(s, nsw, nsb);
    wtrans_kernel<<<dim3(16,16,5), dim3(32,8)>>>(Wq, Wk, Wv, Wg, Wo);
    tc_gemm<<<dim3(8,16,4), 256, 73728>>>(bq, nullptr, -1);

    cudaEventRecord(evJoin, s2);
    cudaStreamWaitEvent(0, evJoin, 0);
    flash_kernel<<<dim3(NSEQ/64, NHEAD), 256, 97280>>>();
    tc_gemm<<<dim3(8,16,1), 256, 73728>>>(bq, out, 4);
}